// round 1
// baseline (speedup 1.0000x reference)
#include <cuda_runtime.h>
#include <math.h>

#define B_  2
#define N_  2048
#define C_  1024
#define H_  16
#define HD_ 64
#define M_  (B_ * N_)      // 4096
#define QKVN (3 * C_)      // 3072

// Scratch (static device globals — no allocation in kernel_launch)
static __device__ float g_qkv[M_ * QKVN];  // [4096, 3072]
static __device__ float g_o[M_ * C_];      // [4096, 1024]  attention output, [B,N,C] layout

// ---------------------------------------------------------------------------
// Tiled SGEMM: C[M,N] = A[M,K] @ B[K,N] (+ bias). BM=BN=128, BK=8, 256 thr,
// 8x8 microtile per thread (split 4+4 to keep float4 smem reads conflict-free).
// M % 128 == 0, N % 128 == 0, K % 8 == 0 assumed.
// ---------------------------------------------------------------------------
template <bool HAS_BIAS>
__global__ __launch_bounds__(256) void sgemm128(
    const float* __restrict__ A, const float* __restrict__ Bm,
    const float* __restrict__ bias, float* __restrict__ Cm,
    int M, int N, int K)
{
    __shared__ float As[8][128];
    __shared__ float Bs[8][128];

    const int tid = threadIdx.x;
    const int tx = tid & 15;
    const int ty = tid >> 4;
    const int brow = blockIdx.y * 128;
    const int bcol = blockIdx.x * 128;

    // global load mapping
    const int a_r = tid >> 1;          // 0..127
    const int a_c = (tid & 1) * 4;     // 0 or 4
    const int b_r = tid >> 5;          // 0..7
    const int b_c = (tid & 31) * 4;    // 0..124

    const float* Aptr = A + (size_t)(brow + a_r) * K + a_c;
    const float* Bptr = Bm + (size_t)b_r * N + bcol + b_c;

    float acc[8][8];
#pragma unroll
    for (int i = 0; i < 8; i++)
#pragma unroll
        for (int j = 0; j < 8; j++) acc[i][j] = 0.f;

    float4 av = *(const float4*)(Aptr);
    float4 bv = *(const float4*)(Bptr);

    for (int k0 = 0; k0 < K; k0 += 8) {
        __syncthreads();
        As[a_c + 0][a_r] = av.x;
        As[a_c + 1][a_r] = av.y;
        As[a_c + 2][a_r] = av.z;
        As[a_c + 3][a_r] = av.w;
        *(float4*)&Bs[b_r][b_c] = bv;
        __syncthreads();

        if (k0 + 8 < K) {
            av = *(const float4*)(Aptr + (k0 + 8));
            bv = *(const float4*)(Bptr + (size_t)(k0 + 8) * N);
        }

#pragma unroll
        for (int kk = 0; kk < 8; kk++) {
            float ra[8], rb[8];
            *(float4*)&ra[0] = *(const float4*)&As[kk][ty * 4];
            *(float4*)&ra[4] = *(const float4*)&As[kk][64 + ty * 4];
            *(float4*)&rb[0] = *(const float4*)&Bs[kk][tx * 4];
            *(float4*)&rb[4] = *(const float4*)&Bs[kk][64 + tx * 4];
#pragma unroll
            for (int i = 0; i < 8; i++)
#pragma unroll
                for (int j = 0; j < 8; j++)
                    acc[i][j] += ra[i] * rb[j];
        }
    }

    float4 bias0 = make_float4(0.f, 0.f, 0.f, 0.f);
    float4 bias1 = make_float4(0.f, 0.f, 0.f, 0.f);
    if (HAS_BIAS) {
        bias0 = *(const float4*)(bias + bcol + tx * 4);
        bias1 = *(const float4*)(bias + bcol + 64 + tx * 4);
    }

#pragma unroll
    for (int i = 0; i < 8; i++) {
        int row = brow + ((i < 4) ? (ty * 4 + i) : (64 + ty * 4 + (i - 4)));
        float* cp = Cm + (size_t)row * N + bcol;
        float4 v0 = make_float4(acc[i][0] + bias0.x, acc[i][1] + bias0.y,
                                acc[i][2] + bias0.z, acc[i][3] + bias0.w);
        float4 v1 = make_float4(acc[i][4] + bias1.x, acc[i][5] + bias1.y,
                                acc[i][6] + bias1.z, acc[i][7] + bias1.w);
        *(float4*)(cp + tx * 4) = v0;
        *(float4*)(cp + 64 + tx * 4) = v1;
    }
}

// ---------------------------------------------------------------------------
// LayerNorm on q and k rows of g_qkv in place. One warp per row of hd=64.
// Also applies the hd^-0.5 scale to q. Total rows = 2 * M_ * H_ = 131072.
// ---------------------------------------------------------------------------
__global__ __launch_bounds__(256) void ln_qk(
    float* __restrict__ qkv,
    const float* __restrict__ qw, const float* __restrict__ qb,
    const float* __restrict__ kw, const float* __restrict__ kb)
{
    int gwarp = (blockIdx.x * blockDim.x + threadIdx.x) >> 5;
    int lane = threadIdx.x & 31;
    const int QROWS = M_ * H_;   // 65536
    bool isQ = gwarp < QROWS;
    int r = isQ ? gwarp : gwarp - QROWS;
    int bn = r >> 4;             // r / H_
    int h = r & 15;
    float* ptr = qkv + (size_t)bn * QKVN + (isQ ? 0 : C_) + h * HD_;

    float x0 = ptr[lane];
    float x1 = ptr[lane + 32];
    float s = x0 + x1;
#pragma unroll
    for (int o = 16; o > 0; o >>= 1) s += __shfl_xor_sync(0xffffffffu, s, o);
    float mu = s * (1.0f / 64.0f);
    float d0 = x0 - mu, d1 = x1 - mu;
    float v = d0 * d0 + d1 * d1;
#pragma unroll
    for (int o = 16; o > 0; o >>= 1) v += __shfl_xor_sync(0xffffffffu, v, o);
    float rinv = rsqrtf(v * (1.0f / 64.0f) + 1e-5f);

    const float* w = isQ ? qw : kw;
    const float* bb = isQ ? qb : kb;
    float sc = isQ ? 0.125f : 1.0f;   // hd^-0.5 = 1/8
    ptr[lane]      = (d0 * rinv * w[lane]      + bb[lane])      * sc;
    ptr[lane + 32] = (d1 * rinv * w[lane + 32] + bb[lane + 32]) * sc;
}

// ---------------------------------------------------------------------------
// Flash attention (fp32). Block = 64 q-rows of one (b,h). KV tiles of 64 rows.
// Thread grid 16x16; each thread owns a 4-row x 4-col microtile.
// smem: Qs[64][64], Kt[64(d)][64(c)] (transposed K), Vs[64][64], Ps[64][64].
// 64 KB dynamic smem.
// ---------------------------------------------------------------------------
__global__ __launch_bounds__(256) void attn_kernel(
    const float* __restrict__ qkv, float* __restrict__ o)
{
    extern __shared__ float sm[];
    float* Qs = sm;              // 4096
    float* Kt = sm + 4096;       // 4096  Kt[d*64 + c]
    float* Vs = sm + 8192;       // 4096  Vs[m*64 + col]
    float* Ps = sm + 12288;      // 4096  Ps[row*64 + m]

    const int tid = threadIdx.x;
    const int tx = tid & 15;
    const int ty = tid >> 4;
    const int bh = blockIdx.y;
    const int b = bh >> 4;
    const int h = bh & 15;
    const int q0 = blockIdx.x * 64;

    const float* qbase = qkv + (size_t)(b * N_) * QKVN + h * HD_;
    const float* kbase = qbase + C_;
    const float* vbase = qbase + 2 * C_;

    // loader mapping: thread -> row lr (0..63), 16-float segment ls
    const int lr = tid >> 2;
    const int ls = (tid & 3) * 16;

    // load Q tile
    {
        const float* src = qbase + (size_t)(q0 + lr) * QKVN + ls;
        float4* dst = (float4*)(Qs + lr * 64 + ls);
#pragma unroll
        for (int j = 0; j < 4; j++) dst[j] = ((const float4*)src)[j];
    }

    float m_r[4], l_r[4];
    float4 acc4[4];
#pragma unroll
    for (int r = 0; r < 4; r++) {
        m_r[r] = -INFINITY;
        l_r[r] = 0.f;
        acc4[r] = make_float4(0.f, 0.f, 0.f, 0.f);
    }

    for (int kv0 = 0; kv0 < N_; kv0 += 64) {
        __syncthreads();   // previous P@V done (and Q visible on first iter)

        // load K (transposed into Kt) and V (natural)
        {
            const float* ksrc = kbase + (size_t)(kv0 + lr) * QKVN + ls;
#pragma unroll
            for (int j = 0; j < 4; j++) {
                float4 kv = ((const float4*)ksrc)[j];
                Kt[(ls + j * 4 + 0) * 64 + lr] = kv.x;
                Kt[(ls + j * 4 + 1) * 64 + lr] = kv.y;
                Kt[(ls + j * 4 + 2) * 64 + lr] = kv.z;
                Kt[(ls + j * 4 + 3) * 64 + lr] = kv.w;
            }
            const float* vsrc = vbase + (size_t)(kv0 + lr) * QKVN + ls;
            float4* vdst = (float4*)(Vs + lr * 64 + ls);
#pragma unroll
            for (int j = 0; j < 4; j++) vdst[j] = ((const float4*)vsrc)[j];
        }
        __syncthreads();

        // --- S = Q @ K^T (scale already folded into Q) ---
        float4 s4[4];
#pragma unroll
        for (int r = 0; r < 4; r++) s4[r] = make_float4(0.f, 0.f, 0.f, 0.f);

#pragma unroll 4
        for (int d = 0; d < 64; d += 4) {
            float4 k0 = *(const float4*)(Kt + (d + 0) * 64 + tx * 4);
            float4 k1 = *(const float4*)(Kt + (d + 1) * 64 + tx * 4);
            float4 k2 = *(const float4*)(Kt + (d + 2) * 64 + tx * 4);
            float4 k3 = *(const float4*)(Kt + (d + 3) * 64 + tx * 4);
#pragma unroll
            for (int r = 0; r < 4; r++) {
                float4 q = *(const float4*)(Qs + (ty * 4 + r) * 64 + d);
                s4[r].x += q.x * k0.x + q.y * k1.x + q.z * k2.x + q.w * k3.x;
                s4[r].y += q.x * k0.y + q.y * k1.y + q.z * k2.y + q.w * k3.y;
                s4[r].z += q.x * k0.z + q.y * k1.z + q.z * k2.z + q.w * k3.z;
                s4[r].w += q.x * k0.w + q.y * k1.w + q.z * k2.w + q.w * k3.w;
            }
        }

        // --- online softmax ---
#pragma unroll
        for (int r = 0; r < 4; r++) {
            float mx = fmaxf(fmaxf(s4[r].x, s4[r].y), fmaxf(s4[r].z, s4[r].w));
#pragma unroll
            for (int off = 8; off > 0; off >>= 1)
                mx = fmaxf(mx, __shfl_xor_sync(0xffffffffu, mx, off, 16));
            float mnew = fmaxf(m_r[r], mx);
            float corr = __expf(m_r[r] - mnew);
            m_r[r] = mnew;
            float px = __expf(s4[r].x - mnew);
            float py = __expf(s4[r].y - mnew);
            float pz = __expf(s4[r].z - mnew);
            float pw = __expf(s4[r].w - mnew);
            float rs = px + py + pz + pw;
#pragma unroll
            for (int off = 8; off > 0; off >>= 1)
                rs += __shfl_xor_sync(0xffffffffu, rs, off, 16);
            l_r[r] = l_r[r] * corr + rs;
            acc4[r].x *= corr; acc4[r].y *= corr; acc4[r].z *= corr; acc4[r].w *= corr;
            *(float4*)(Ps + (ty * 4 + r) * 64 + tx * 4) = make_float4(px, py, pz, pw);
        }
        __syncthreads();

        // --- O += P @ V ---
#pragma unroll 4
        for (int m = 0; m < 64; m += 4) {
            float4 v0 = *(const float4*)(Vs + (m + 0) * 64 + tx * 4);
            float4 v1 = *(const float4*)(Vs + (m + 1) * 64 + tx * 4);
            float4 v2 = *(const float4*)(Vs + (m + 2) * 64 + tx * 4);
            float4 v3 = *(const float4*)(Vs + (m + 3) * 64 + tx * 4);
#pragma unroll
            for (int r = 0; r < 4; r++) {
                float4 p = *(const float4*)(Ps + (ty * 4 + r) * 64 + m);
                acc4[r].x += p.x * v0.x + p.y * v1.x + p.z * v2.x + p.w * v3.x;
                acc4[r].y += p.x * v0.y + p.y * v1.y + p.z * v2.y + p.w * v3.y;
                acc4[r].z += p.x * v0.z + p.y * v1.z + p.z * v2.z + p.w * v3.z;
                acc4[r].w += p.x * v0.w + p.y * v1.w + p.z * v2.w + p.w * v3.w;
            }
        }
    }

    // epilogue: normalize and write [B,N,C] layout
#pragma unroll
    for (int r = 0; r < 4; r++) {
        float inv = 1.0f / l_r[r];
        float4 v = acc4[r];
        v.x *= inv; v.y *= inv; v.z *= inv; v.w *= inv;
        int row = q0 + ty * 4 + r;
        *(float4*)(o + (size_t)(b * N_ + row) * C_ + h * HD_ + tx * 4) = v;
    }
}

// ---------------------------------------------------------------------------
// Launch
// ---------------------------------------------------------------------------
extern "C" void kernel_launch(void* const* d_in, const int* in_sizes, int n_in,
                              void* d_out, int out_size)
{
    const float* x     = (const float*)d_in[0];
    const float* Wqkv  = (const float*)d_in[1];
    const float* qnw   = (const float*)d_in[2];
    const float* qnb   = (const float*)d_in[3];
    const float* knw   = (const float*)d_in[4];
    const float* knb   = (const float*)d_in[5];
    const float* Wproj = (const float*)d_in[6];
    const float* bproj = (const float*)d_in[7];
    float* out = (float*)d_out;

    float* qkv = nullptr;
    float* oatt = nullptr;
    cudaGetSymbolAddress((void**)&qkv, g_qkv);
    cudaGetSymbolAddress((void**)&oatt, g_o);

    // 1) QKV GEMM: [4096,1024] @ [1024,3072]
    {
        dim3 grid(QKVN / 128, M_ / 128);
        sgemm128<false><<<grid, 256>>>(x, Wqkv, nullptr, qkv, M_, QKVN, C_);
    }

    // 2) LayerNorm q & k (in place, q pre-scaled)
    {
        int total_warps = 2 * M_ * H_;           // 131072
        int blocks = total_warps / 8;            // 256 threads = 8 warps
        ln_qk<<<blocks, 256>>>(qkv, qnw, qnb, knw, knb);
    }

    // 3) Flash attention
    {
        cudaFuncSetAttribute(attn_kernel,
                             cudaFuncAttributeMaxDynamicSharedMemorySize, 65536);
        dim3 grid(N_ / 64, B_ * H_);
        attn_kernel<<<grid, 256, 65536>>>(qkv, oatt);
    }

    // 4) Proj GEMM + bias: [4096,1024] @ [1024,1024]
    {
        dim3 grid(C_ / 128, M_ / 128);
        sgemm128<true><<<grid, 256>>>(oatt, Wproj, bproj, out, M_, C_, C_);
    }
}

// round 3
// speedup vs baseline: 1.8200x; 1.8200x over previous
#include <cuda_runtime.h>
#include <cuda_bf16.h>
#include <math.h>
#include <stdint.h>

#define B_  2
#define N_  2048
#define C_  1024
#define H_  16
#define HD_ 64
#define M_  (B_ * N_)      // 4096
#define QKVN (3 * C_)      // 3072
#define LOG2E 1.4426950408889634f

// ---------------- scratch (static device globals) ----------------
static __device__ __align__(256) float g_qkv[M_ * QKVN];             // fp32 qkv
static __device__ __align__(256) __nv_bfloat16 g_xh[M_ * C_];        // x split planes
static __device__ __align__(256) __nv_bfloat16 g_xl[M_ * C_];
static __device__ __align__(256) __nv_bfloat16 g_oh[M_ * C_];        // attn-out split planes [M,C]
static __device__ __align__(256) __nv_bfloat16 g_ol[M_ * C_];
static __device__ __align__(256) __nv_bfloat16 g_wqkvT_h[QKVN * C_]; // W_qkv^T [3072,1024]
static __device__ __align__(256) __nv_bfloat16 g_wqkvT_l[QKVN * C_];
static __device__ __align__(256) __nv_bfloat16 g_wprojT_h[C_ * C_];  // W_proj^T [1024,1024]
static __device__ __align__(256) __nv_bfloat16 g_wprojT_l[C_ * C_];
// q/k/v planes in [B,H,N,64] layout (q LN'd+scaled, k LN'd, v plain)
static __device__ __align__(256) __nv_bfloat16 g_qh[M_ * C_ / 1];    // B*H*N*64 = 4M elems
static __device__ __align__(256) __nv_bfloat16 g_ql[M_ * C_];
static __device__ __align__(256) __nv_bfloat16 g_kh[M_ * C_];
static __device__ __align__(256) __nv_bfloat16 g_kl[M_ * C_];
static __device__ __align__(256) __nv_bfloat16 g_vh[M_ * C_];
static __device__ __align__(256) __nv_bfloat16 g_vl[M_ * C_];

// ---------------- helpers ----------------
__device__ __forceinline__ uint32_t smem_u32(const void* p) {
    uint32_t a;
    asm("{ .reg .u64 t; cvta.to.shared.u64 t, %1; cvt.u32.u64 %0, t; }" : "=r"(a) : "l"(p));
    return a;
}
__device__ __forceinline__ uint32_t swz(uint32_t o) { return o ^ ((o >> 3) & 0x70); }

__device__ __forceinline__ void cp16(uint32_t dst, const void* src) {
    asm volatile("cp.async.cg.shared.global [%0], [%1], 16;" :: "r"(dst), "l"(src) : "memory");
}
#define CP_COMMIT() asm volatile("cp.async.commit_group;" ::: "memory")
#define CP_WAIT(N)  asm volatile("cp.async.wait_group %0;" :: "n"(N) : "memory")

__device__ __forceinline__ void ldsm4(uint32_t* r, uint32_t a) {
    asm volatile("ldmatrix.sync.aligned.m8n8.x4.shared.b16 {%0,%1,%2,%3}, [%4];"
                 : "=r"(r[0]), "=r"(r[1]), "=r"(r[2]), "=r"(r[3]) : "r"(a));
}
__device__ __forceinline__ void ldsm2(uint32_t* r, uint32_t a) {
    asm volatile("ldmatrix.sync.aligned.m8n8.x2.shared.b16 {%0,%1}, [%2];"
                 : "=r"(r[0]), "=r"(r[1]) : "r"(a));
}
__device__ __forceinline__ void ldsm2t(uint32_t* r, uint32_t a) {
    asm volatile("ldmatrix.sync.aligned.m8n8.x2.trans.shared.b16 {%0,%1}, [%2];"
                 : "=r"(r[0]), "=r"(r[1]) : "r"(a));
}
__device__ __forceinline__ void mma16816(float* c, const uint32_t* a, const uint32_t* b) {
    asm volatile(
        "mma.sync.aligned.m16n8k16.row.col.f32.bf16.bf16.f32 "
        "{%0,%1,%2,%3}, {%4,%5,%6,%7}, {%8,%9}, {%0,%1,%2,%3};"
        : "+f"(c[0]), "+f"(c[1]), "+f"(c[2]), "+f"(c[3])
        : "r"(a[0]), "r"(a[1]), "r"(a[2]), "r"(a[3]), "r"(b[0]), "r"(b[1]));
}
// pack (lo, hi) floats into bf16x2 (lo in low 16 bits)
__device__ __forceinline__ uint32_t pack2(float lo, float hi) {
    uint32_t r;
    asm("cvt.rn.bf16x2.f32 %0, %1, %2;" : "=r"(r) : "f"(hi), "f"(lo));
    return r;
}
// split pair (a,b) into hi bf16x2 and residual-lo bf16x2
__device__ __forceinline__ void split2(float a, float b, uint32_t& hi, uint32_t& lo) {
    __nv_bfloat16 xa = __float2bfloat16(a), xb = __float2bfloat16(b);
    hi = pack2(__bfloat162float(xa), __bfloat162float(xb));
    // repack hi via exact floats to guarantee residual consistency
    lo = pack2(a - __bfloat162float(xa), b - __bfloat162float(xb));
}

// ---------------------------------------------------------------------------
// cvt_split: fp32 -> (bf16 hi, bf16 lo) elementwise
// ---------------------------------------------------------------------------
__global__ __launch_bounds__(256) void cvt_split(
    const float* __restrict__ in, __nv_bfloat16* __restrict__ hi,
    __nv_bfloat16* __restrict__ lo, int n4)
{
    int i = blockIdx.x * blockDim.x + threadIdx.x;
    if (i >= n4) return;
    float4 v = ((const float4*)in)[i];
    uint32_t h0, l0, h1, l1;
    split2(v.x, v.y, h0, l0);
    split2(v.z, v.w, h1, l1);
    ((uint32_t*)hi)[2 * i] = h0; ((uint32_t*)hi)[2 * i + 1] = h1;
    ((uint32_t*)lo)[2 * i] = l0; ((uint32_t*)lo)[2 * i + 1] = l1;
}

// ---------------------------------------------------------------------------
// cvt_transpose_split: W[K,N] fp32 -> out_hi/lo [N,K] bf16
// ---------------------------------------------------------------------------
__global__ __launch_bounds__(256) void cvt_transpose_split(
    const float* __restrict__ W, __nv_bfloat16* __restrict__ oh,
    __nv_bfloat16* __restrict__ ol, int Kw, int Nw)
{
    __shared__ float t[32][33];
    int tx = threadIdx.x, ty = threadIdx.y;
    int n0 = blockIdx.x * 32, k0 = blockIdx.y * 32;
#pragma unroll
    for (int j = 0; j < 4; j++)
        t[ty + 8 * j][tx] = W[(size_t)(k0 + ty + 8 * j) * Nw + n0 + tx];
    __syncthreads();
#pragma unroll
    for (int j = 0; j < 4; j++) {
        float v = t[tx][ty + 8 * j];
        __nv_bfloat16 h = __float2bfloat16(v);
        __nv_bfloat16 l = __float2bfloat16(v - __bfloat162float(h));
        size_t idx = (size_t)(n0 + ty + 8 * j) * Kw + k0 + tx;
        oh[idx] = h; ol[idx] = l;
    }
}

// ---------------------------------------------------------------------------
// HMMA split-bf16 GEMM: C[M,N] = A[M,K] @ Bt[N,K]^T (+bias)
// CTA 128x128, BK=32, 8 warps (warp tile 32x64), cp.async double buffer.
// smem stage: A 128rows x [hi64B|lo64B]=16KB, B same = 32KB; 2 stages = 64KB.
// ---------------------------------------------------------------------------
#define HG_STAGE 32768

template <bool HAS_BIAS>
__global__ __launch_bounds__(256) void hgemm(
    const __nv_bfloat16* __restrict__ Ah, const __nv_bfloat16* __restrict__ Al,
    const __nv_bfloat16* __restrict__ Bh, const __nv_bfloat16* __restrict__ Bl,
    const float* __restrict__ bias, float* __restrict__ Cm, int N, int K)
{
    extern __shared__ __align__(1024) char smem[];
    const uint32_t sbase = smem_u32(smem);
    const int tid = threadIdx.x;
    const int lane = tid & 31;
    const int wid = tid >> 5;
    const int wm = (wid >> 1) * 32;   // warp row offset (4 warps in m)
    const int wn = (wid & 1) * 64;    // warp col offset (2 warps in n)
    const int brow = blockIdx.y * 128;
    const int bcol = blockIdx.x * 128;

    // loader mapping
    const int lrow = tid >> 1;
    const int lpl = tid & 1;          // 0 = hi, 1 = lo
    const __nv_bfloat16* Asrc0 = (lpl ? Al : Ah) + (size_t)(brow + lrow) * K;
    const __nv_bfloat16* Bsrc0 = (lpl ? Bl : Bh) + (size_t)(bcol + lrow) * K;
    uint32_t sdst[4];
#pragma unroll
    for (int j = 0; j < 4; j++) sdst[j] = swz(lrow * 128 + lpl * 64 + j * 16);

    float acc[2][8][4];
#pragma unroll
    for (int mt = 0; mt < 2; mt++)
#pragma unroll
        for (int j = 0; j < 8; j++)
#pragma unroll
            for (int i = 0; i < 4; i++) acc[mt][j][i] = 0.f;

    const int T = K >> 5;   // 32 chunks

    // prologue: stages 0,1
#pragma unroll
    for (int s = 0; s < 2; s++) {
        uint32_t sA = sbase + s * HG_STAGE;
        uint32_t sB = sA + 16384;
#pragma unroll
        for (int j = 0; j < 4; j++) {
            cp16(sA + sdst[j], Asrc0 + s * 32 + j * 8);
            cp16(sB + sdst[j], Bsrc0 + s * 32 + j * 8);
        }
        CP_COMMIT();
    }

    for (int t = 0; t < T; t++) {
        if (t == T - 1) { CP_WAIT(0); } else { CP_WAIT(1); }
        __syncthreads();

        const uint32_t sA = sbase + (t & 1) * HG_STAGE;
        const uint32_t sB = sA + 16384;

#pragma unroll
        for (int ks = 0; ks < 2; ks++) {
            // B fragments for this warp's 64 cols, both planes
            uint32_t bfh[8][2], bfl[8][2];
#pragma unroll
            for (int j = 0; j < 8; j++) {
                uint32_t off = swz((wn + j * 8 + (lane & 7)) * 128 +
                                   ks * 32 + ((lane >> 3) & 1) * 16);
                ldsm2(bfh[j], sB + off);
                uint32_t offl = swz((wn + j * 8 + (lane & 7)) * 128 + 64 +
                                    ks * 32 + ((lane >> 3) & 1) * 16);
                ldsm2(bfl[j], sB + offl);
            }
#pragma unroll
            for (int mt = 0; mt < 2; mt++) {
                uint32_t ah[4], al[4];
                uint32_t aoff = swz((wm + mt * 16 + (lane & 15)) * 128 +
                                    ks * 32 + (lane >> 4) * 16);
                ldsm4(ah, sA + aoff);
                uint32_t aoffl = swz((wm + mt * 16 + (lane & 15)) * 128 + 64 +
                                     ks * 32 + (lane >> 4) * 16);
                ldsm4(al, sA + aoffl);
#pragma unroll
                for (int j = 0; j < 8; j++) {
                    mma16816(acc[mt][j], ah, bfh[j]);
                    mma16816(acc[mt][j], ah, bfl[j]);
                    mma16816(acc[mt][j], al, bfh[j]);
                }
            }
        }
        __syncthreads();
        if (t + 2 < T) {
            uint32_t sA2 = sbase + (t & 1) * HG_STAGE;
            uint32_t sB2 = sA2 + 16384;
#pragma unroll
            for (int j = 0; j < 4; j++) {
                cp16(sA2 + sdst[j], Asrc0 + (t + 2) * 32 + j * 8);
                cp16(sB2 + sdst[j], Bsrc0 + (t + 2) * 32 + j * 8);
            }
            CP_COMMIT();
        }
    }

    // epilogue
#pragma unroll
    for (int mt = 0; mt < 2; mt++) {
        int r0 = brow + wm + mt * 16 + (lane >> 2);
#pragma unroll
        for (int j = 0; j < 8; j++) {
            int col = bcol + wn + j * 8 + (lane & 3) * 2;
            float bx = 0.f, by = 0.f;
            if (HAS_BIAS) { bx = bias[col]; by = bias[col + 1]; }
            float2 v0 = make_float2(acc[mt][j][0] + bx, acc[mt][j][1] + by);
            float2 v1 = make_float2(acc[mt][j][2] + bx, acc[mt][j][3] + by);
            *(float2*)(Cm + (size_t)r0 * N + col) = v0;
            *(float2*)(Cm + (size_t)(r0 + 8) * N + col) = v1;
        }
    }
}

// ---------------------------------------------------------------------------
// ln_split: LayerNorm q,k + plain v; write bf16 hi/lo planes [B,H,N,64].
// q also scaled by hd^-0.5 * log2(e). One warp per 64-elem row.
// ---------------------------------------------------------------------------
__global__ __launch_bounds__(256) void ln_split(
    const float* __restrict__ qkv,
    const float* __restrict__ qw, const float* __restrict__ qb,
    const float* __restrict__ kw, const float* __restrict__ kb,
    __nv_bfloat16* __restrict__ qh, __nv_bfloat16* __restrict__ ql,
    __nv_bfloat16* __restrict__ kh, __nv_bfloat16* __restrict__ kl,
    __nv_bfloat16* __restrict__ vh, __nv_bfloat16* __restrict__ vl)
{
    int gwarp = (blockIdx.x * blockDim.x + threadIdx.x) >> 5;
    int lane = threadIdx.x & 31;
    const int ROWS = M_ * H_;                 // 65536
    int mtx = (gwarp >= 2 * ROWS) ? 2 : (gwarp >= ROWS ? 1 : 0);
    int r = gwarp - mtx * ROWS;
    int bn = r >> 4;
    int h = r & 15;
    const float* src = qkv + (size_t)bn * QKVN + mtx * C_ + h * HD_;

    float x0 = src[lane];
    float x1 = src[lane + 32];

    if (mtx < 2) {
        float s = x0 + x1;
#pragma unroll
        for (int o = 16; o > 0; o >>= 1) s += __shfl_xor_sync(0xffffffffu, s, o);
        float mu = s * (1.0f / 64.0f);
        float d0 = x0 - mu, d1 = x1 - mu;
        float v = d0 * d0 + d1 * d1;
#pragma unroll
        for (int o = 16; o > 0; o >>= 1) v += __shfl_xor_sync(0xffffffffu, v, o);
        float rinv = rsqrtf(v * (1.0f / 64.0f) + 1e-5f);
        const float* w = mtx == 0 ? qw : kw;
        const float* bb = mtx == 0 ? qb : kb;
        float sc = mtx == 0 ? (0.125f * LOG2E) : 1.0f;
        x0 = (d0 * rinv * w[lane] + bb[lane]) * sc;
        x1 = (d1 * rinv * w[lane + 32] + bb[lane + 32]) * sc;
    }

    int b = bn >> 11;           // N_=2048 rows per batch
    int n = bn & (N_ - 1);
    size_t dst = ((size_t)(b * H_ + h) * N_ + n) * HD_;
    __nv_bfloat16* ph = mtx == 0 ? qh : (mtx == 1 ? kh : vh);
    __nv_bfloat16* pl = mtx == 0 ? ql : (mtx == 1 ? kl : vl);
    __nv_bfloat16 h0 = __float2bfloat16(x0);
    __nv_bfloat16 h1 = __float2bfloat16(x1);
    ph[dst + lane] = h0;
    ph[dst + lane + 32] = h1;
    pl[dst + lane] = __float2bfloat16(x0 - __bfloat162float(h0));
    pl[dst + lane + 32] = __float2bfloat16(x1 - __bfloat162float(h1));
}

// ---------------------------------------------------------------------------
// HMMA flash attention. CTA = 4 warps, 64 q rows of one (b,h); kv tiles of 64.
// smem: Q (hi 8KB | lo 8KB) + 2 stages x (K 16KB + V 16KB) = 80KB.
// Writes O as bf16 hi/lo planes in [M, C] layout for the proj GEMM.
// ---------------------------------------------------------------------------
#define AT_KV_STAGE 32768
#define AT_SMEM (16384 + 2 * AT_KV_STAGE)

__global__ __launch_bounds__(128) void attn_hmma(
    const __nv_bfloat16* __restrict__ qh, const __nv_bfloat16* __restrict__ ql,
    const __nv_bfloat16* __restrict__ kh, const __nv_bfloat16* __restrict__ kl,
    const __nv_bfloat16* __restrict__ vh, const __nv_bfloat16* __restrict__ vl,
    __nv_bfloat16* __restrict__ OH, __nv_bfloat16* __restrict__ OL)
{
    extern __shared__ __align__(1024) char smem[];
    const uint32_t sbase = smem_u32(smem);
    const int tid = threadIdx.x;
    const int lane = tid & 31;
    const int w = tid >> 5;
    const int bh = blockIdx.y;
    const int q0 = blockIdx.x * 64;
    const size_t base = (size_t)bh * N_ * HD_;

    // ---- prologue loads: Q + KV stage 0, then KV stage 1 ----
    {
#pragma unroll
        for (int j = 0; j < 8; j++) {
            int id = tid * 8 + j;            // 1024 chunks (2 planes x 64 rows x 8)
            int pl = id >> 9, rem = id & 511, row = rem >> 3, ch = rem & 7;
            const __nv_bfloat16* src = (pl ? ql : qh) + base + (size_t)(q0 + row) * HD_ + ch * 8;
            cp16(sbase + pl * 8192 + swz(row * 128 + ch * 16), src);
        }
#pragma unroll
        for (int j = 0; j < 8; j++) {
            int id = tid * 8 + j;
            int pl = id >> 9, rem = id & 511, row = rem >> 3, ch = rem & 7;
            cp16(sbase + 16384 + pl * 8192 + swz(row * 128 + ch * 16),
                 (pl ? kl : kh) + base + (size_t)row * HD_ + ch * 8);
            cp16(sbase + 16384 + 16384 + pl * 8192 + swz(row * 128 + ch * 16),
                 (pl ? vl : vh) + base + (size_t)row * HD_ + ch * 8);
        }
        CP_COMMIT();
#pragma unroll
        for (int j = 0; j < 8; j++) {
            int id = tid * 8 + j;
            int pl = id >> 9, rem = id & 511, row = rem >> 3, ch = rem & 7;
            cp16(sbase + 16384 + AT_KV_STAGE + pl * 8192 + swz(row * 128 + ch * 16),
                 (pl ? kl : kh) + base + (size_t)(64 + row) * HD_ + ch * 8);
            cp16(sbase + 16384 + AT_KV_STAGE + 16384 + pl * 8192 + swz(row * 128 + ch * 16),
                 (pl ? vl : vh) + base + (size_t)(64 + row) * HD_ + ch * 8);
        }
        CP_COMMIT();
    }

    uint32_t qfh[4][4], qfl[4][4];
    float oac[8][4];
#pragma unroll
    for (int j = 0; j < 8; j++)
#pragma unroll
        for (int i = 0; i < 4; i++) oac[j][i] = 0.f;
    float m0 = -INFINITY, m1 = -INFINITY, l0 = 0.f, l1 = 0.f;

    const int T = N_ / 64;   // 32
    for (int t = 0; t < T; t++) {
        if (t == T - 1) { CP_WAIT(0); } else { CP_WAIT(1); }
        __syncthreads();

        if (t == 0) {
            // load Q fragments (resident for whole kernel)
#pragma unroll
            for (int kt = 0; kt < 4; kt++) {
                uint32_t off = swz((w * 16 + (lane & 15)) * 128 + kt * 32 + (lane >> 4) * 16);
                ldsm4(qfh[kt], sbase + off);
                ldsm4(qfl[kt], sbase + 8192 + off);
            }
        }

        const uint32_t sK = sbase + 16384 + (t & 1) * AT_KV_STAGE;
        const uint32_t sV = sK + 16384;

        // ---- S = Q @ K^T ----
        float s[8][4];
#pragma unroll
        for (int j = 0; j < 8; j++)
#pragma unroll
            for (int i = 0; i < 4; i++) s[j][i] = 0.f;
#pragma unroll
        for (int kt = 0; kt < 4; kt++) {
#pragma unroll
            for (int j = 0; j < 8; j++) {
                uint32_t off = swz((j * 8 + (lane & 7)) * 128 + kt * 32 + ((lane >> 3) & 1) * 16);
                uint32_t kfh[2], kfl[2];
                ldsm2(kfh, sK + off);
                ldsm2(kfl, sK + 8192 + off);
                mma16816(s[j], qfh[kt], kfh);
                mma16816(s[j], qfh[kt], kfl);
                mma16816(s[j], qfl[kt], kfh);
            }
        }

        // ---- online softmax (log2 domain) ----
        float mx0 = -INFINITY, mx1 = -INFINITY;
#pragma unroll
        for (int j = 0; j < 8; j++) {
            mx0 = fmaxf(mx0, fmaxf(s[j][0], s[j][1]));
            mx1 = fmaxf(mx1, fmaxf(s[j][2], s[j][3]));
        }
        mx0 = fmaxf(mx0, __shfl_xor_sync(0xffffffffu, mx0, 1));
        mx0 = fmaxf(mx0, __shfl_xor_sync(0xffffffffu, mx0, 2));
        mx1 = fmaxf(mx1, __shfl_xor_sync(0xffffffffu, mx1, 1));
        mx1 = fmaxf(mx1, __shfl_xor_sync(0xffffffffu, mx1, 2));
        float mn0 = fmaxf(m0, mx0), mn1 = fmaxf(m1, mx1);
        float c0 = exp2f(m0 - mn0), c1 = exp2f(m1 - mn1);
        m0 = mn0; m1 = mn1;
        float rs0 = 0.f, rs1 = 0.f;
#pragma unroll
        for (int j = 0; j < 8; j++) {
            s[j][0] = exp2f(s[j][0] - mn0);
            s[j][1] = exp2f(s[j][1] - mn0);
            s[j][2] = exp2f(s[j][2] - mn1);
            s[j][3] = exp2f(s[j][3] - mn1);
            rs0 += s[j][0] + s[j][1];
            rs1 += s[j][2] + s[j][3];
        }
        rs0 += __shfl_xor_sync(0xffffffffu, rs0, 1);
        rs0 += __shfl_xor_sync(0xffffffffu, rs0, 2);
        rs1 += __shfl_xor_sync(0xffffffffu, rs1, 1);
        rs1 += __shfl_xor_sync(0xffffffffu, rs1, 2);
        l0 = l0 * c0 + rs0;
        l1 = l1 * c1 + rs1;
#pragma unroll
        for (int j = 0; j < 8; j++) {
            oac[j][0] *= c0; oac[j][1] *= c0;
            oac[j][2] *= c1; oac[j][3] *= c1;
        }

        // ---- O += P @ V ----
#pragma unroll
        for (int kt2 = 0; kt2 < 4; kt2++) {
            uint32_t pfh[4], pfl[4];
            split2(s[2 * kt2][0],     s[2 * kt2][1],     pfh[0], pfl[0]);
            split2(s[2 * kt2][2],     s[2 * kt2][3],     pfh[1], pfl[1]);
            split2(s[2 * kt2 + 1][0], s[2 * kt2 + 1][1], pfh[2], pfl[2]);
            split2(s[2 * kt2 + 1][2], s[2 * kt2 + 1][3], pfh[3], pfl[3]);
#pragma unroll
            for (int hj = 0; hj < 8; hj++) {
                uint32_t off = swz((kt2 * 16 + (lane & 15)) * 128 + hj * 16);
                uint32_t vfh[2], vfl[2];
                ldsm2t(vfh, sV + off);
                ldsm2t(vfl, sV + 8192 + off);
                mma16816(oac[hj], pfh, vfh);
                mma16816(oac[hj], pfh, vfl);
                mma16816(oac[hj], pfl, vfh);
            }
        }

        __syncthreads();
        if (t + 2 < T) {
            const uint32_t sKn = sbase + 16384 + (t & 1) * AT_KV_STAGE;
#pragma unroll
            for (int j = 0; j < 8; j++) {
                int id = tid * 8 + j;
                int pl = id >> 9, rem = id & 511, row = rem >> 3, ch = rem & 7;
                cp16(sKn + pl * 8192 + swz(row * 128 + ch * 16),
                     (pl ? kl : kh) + base + (size_t)((t + 2) * 64 + row) * HD_ + ch * 8);
                cp16(sKn + 16384 + pl * 8192 + swz(row * 128 + ch * 16),
                     (pl ? vl : vh) + base + (size_t)((t + 2) * 64 + row) * HD_ + ch * 8);
            }
            CP_COMMIT();
        }
    }

    // ---- epilogue: normalize, split, write [M,C] planes ----
    float il0 = 1.0f / l0, il1 = 1.0f / l1;
    int b = bh >> 4, h = bh & 15;
    int r0 = q0 + w * 16 + (lane >> 2);
    size_t base0 = ((size_t)(b * N_) + r0) * C_ + h * HD_;
    size_t base1 = base0 + 8 * C_;
#pragma unroll
    for (int hj = 0; hj < 8; hj++) {
        int col = hj * 8 + (lane & 3) * 2;
        uint32_t hi, lo;
        split2(oac[hj][0] * il0, oac[hj][1] * il0, hi, lo);
        *(uint32_t*)(OH + base0 + col) = hi;
        *(uint32_t*)(OL + base0 + col) = lo;
        split2(oac[hj][2] * il1, oac[hj][3] * il1, hi, lo);
        *(uint32_t*)(OH + base1 + col) = hi;
        *(uint32_t*)(OL + base1 + col) = lo;
    }
}

// ---------------------------------------------------------------------------
// Launch
// ---------------------------------------------------------------------------
extern "C" void kernel_launch(void* const* d_in, const int* in_sizes, int n_in,
                              void* d_out, int out_size)
{
    const float* x     = (const float*)d_in[0];
    const float* Wqkv  = (const float*)d_in[1];
    const float* qnw   = (const float*)d_in[2];
    const float* qnb   = (const float*)d_in[3];
    const float* knw   = (const float*)d_in[4];
    const float* knb   = (const float*)d_in[5];
    const float* Wproj = (const float*)d_in[6];
    const float* bproj = (const float*)d_in[7];
    float* out = (float*)d_out;

    float* qkv;
    __nv_bfloat16 *xh, *xl, *oh, *ol, *wqh, *wql, *wph, *wpl;
    __nv_bfloat16 *qh, *ql, *kh, *kl, *vh, *vl;
    cudaGetSymbolAddress((void**)&qkv, g_qkv);
    cudaGetSymbolAddress((void**)&xh, g_xh);
    cudaGetSymbolAddress((void**)&xl, g_xl);
    cudaGetSymbolAddress((void**)&oh, g_oh);
    cudaGetSymbolAddress((void**)&ol, g_ol);
    cudaGetSymbolAddress((void**)&wqh, g_wqkvT_h);
    cudaGetSymbolAddress((void**)&wql, g_wqkvT_l);
    cudaGetSymbolAddress((void**)&wph, g_wprojT_h);
    cudaGetSymbolAddress((void**)&wpl, g_wprojT_l);
    cudaGetSymbolAddress((void**)&qh, g_qh);
    cudaGetSymbolAddress((void**)&ql, g_ql);
    cudaGetSymbolAddress((void**)&kh, g_kh);
    cudaGetSymbolAddress((void**)&kl, g_kl);
    cudaGetSymbolAddress((void**)&vh, g_vh);
    cudaGetSymbolAddress((void**)&vl, g_vl);

    cudaFuncSetAttribute(hgemm<false>, cudaFuncAttributeMaxDynamicSharedMemorySize, 2 * HG_STAGE);
    cudaFuncSetAttribute(hgemm<true>, cudaFuncAttributeMaxDynamicSharedMemorySize, 2 * HG_STAGE);
    cudaFuncSetAttribute(attn_hmma, cudaFuncAttributeMaxDynamicSharedMemorySize, AT_SMEM);

    // 0) split x, transpose+split weights
    cvt_split<<<(M_ * C_ / 4 + 255) / 256, 256>>>(x, xh, xl, M_ * C_ / 4);
    cvt_transpose_split<<<dim3(QKVN / 32, C_ / 32), dim3(32, 8)>>>(Wqkv, wqh, wql, C_, QKVN);
    cvt_transpose_split<<<dim3(C_ / 32, C_ / 32), dim3(32, 8)>>>(Wproj, wph, wpl, C_, C_);

    // 1) QKV GEMM (HMMA): [4096,1024] @ [1024,3072]
    hgemm<false><<<dim3(QKVN / 128, M_ / 128), 256, 2 * HG_STAGE>>>(
        xh, xl, wqh, wql, nullptr, qkv, QKVN, C_);

    // 2) LN q,k + split q/k/v into [B,H,N,64] planes
    ln_split<<<3 * M_ * H_ / 8, 256>>>(qkv, qnw, qnb, knw, knb,
                                       qh, ql, kh, kl, vh, vl);

    // 3) HMMA flash attention -> bf16 hi/lo planes [M,C]
    attn_hmma<<<dim3(N_ / 64, B_ * H_), 128, AT_SMEM>>>(qh, ql, kh, kl, vh, vl, oh, ol);

    // 4) proj GEMM (HMMA) + bias
    hgemm<true><<<dim3(C_ / 128, M_ / 128), 256, 2 * HG_STAGE>>>(
        oh, ol, wph, wpl, bproj, out, C_, C_);
}

// round 4
// speedup vs baseline: 2.1433x; 1.1776x over previous
#include <cuda_runtime.h>
#include <cuda_bf16.h>
#include <math.h>
#include <stdint.h>

#define B_  2
#define N_  2048
#define C_  1024
#define H_  16
#define HD_ 64
#define M_  (B_ * N_)      // 4096
#define QKVN (3 * C_)      // 3072
#define LOG2E 1.4426950408889634f

// ---------------- scratch (static device globals) ----------------
static __device__ __align__(256) float g_qkv[M_ * QKVN];
static __device__ __align__(256) __nv_bfloat16 g_xh[M_ * C_];
static __device__ __align__(256) __nv_bfloat16 g_xl[M_ * C_];
static __device__ __align__(256) __nv_bfloat16 g_oh[M_ * C_];
static __device__ __align__(256) __nv_bfloat16 g_ol[M_ * C_];
static __device__ __align__(256) __nv_bfloat16 g_wqkvT_h[QKVN * C_];
static __device__ __align__(256) __nv_bfloat16 g_wqkvT_l[QKVN * C_];
static __device__ __align__(256) __nv_bfloat16 g_wprojT_h[C_ * C_];
static __device__ __align__(256) __nv_bfloat16 g_wprojT_l[C_ * C_];
static __device__ __align__(256) __nv_bfloat16 g_qh[M_ * C_];
static __device__ __align__(256) __nv_bfloat16 g_ql[M_ * C_];
static __device__ __align__(256) __nv_bfloat16 g_kh[M_ * C_];
static __device__ __align__(256) __nv_bfloat16 g_kl[M_ * C_];
static __device__ __align__(256) __nv_bfloat16 g_vh[M_ * C_];
static __device__ __align__(256) __nv_bfloat16 g_vl[M_ * C_];

// ---------------- helpers ----------------
__device__ __forceinline__ uint32_t smem_u32(const void* p) {
    uint32_t a;
    asm("{ .reg .u64 t; cvta.to.shared.u64 t, %1; cvt.u32.u64 %0, t; }" : "=r"(a) : "l"(p));
    return a;
}
__device__ __forceinline__ uint32_t swz(uint32_t o) { return o ^ ((o >> 3) & 0x70); }

__device__ __forceinline__ void cp16(uint32_t dst, const void* src) {
    asm volatile("cp.async.cg.shared.global [%0], [%1], 16;" :: "r"(dst), "l"(src) : "memory");
}
#define CP_COMMIT() asm volatile("cp.async.commit_group;" ::: "memory")
#define CP_WAIT(N)  asm volatile("cp.async.wait_group %0;" :: "n"(N) : "memory")

__device__ __forceinline__ void ldsm4(uint32_t* r, uint32_t a) {
    asm volatile("ldmatrix.sync.aligned.m8n8.x4.shared.b16 {%0,%1,%2,%3}, [%4];"
                 : "=r"(r[0]), "=r"(r[1]), "=r"(r[2]), "=r"(r[3]) : "r"(a));
}
__device__ __forceinline__ void ldsm4t(uint32_t* r, uint32_t a) {
    asm volatile("ldmatrix.sync.aligned.m8n8.x4.trans.shared.b16 {%0,%1,%2,%3}, [%4];"
                 : "=r"(r[0]), "=r"(r[1]), "=r"(r[2]), "=r"(r[3]) : "r"(a));
}
__device__ __forceinline__ void mma16816(float* c, const uint32_t* a, const uint32_t* b) {
    asm volatile(
        "mma.sync.aligned.m16n8k16.row.col.f32.bf16.bf16.f32 "
        "{%0,%1,%2,%3}, {%4,%5,%6,%7}, {%8,%9}, {%0,%1,%2,%3};"
        : "+f"(c[0]), "+f"(c[1]), "+f"(c[2]), "+f"(c[3])
        : "r"(a[0]), "r"(a[1]), "r"(a[2]), "r"(a[3]), "r"(b[0]), "r"(b[1]));
}
__device__ __forceinline__ uint32_t pack2(float lo, float hi) {
    uint32_t r;
    asm("cvt.rn.bf16x2.f32 %0, %1, %2;" : "=r"(r) : "f"(hi), "f"(lo));
    return r;
}
__device__ __forceinline__ void split2(float a, float b, uint32_t& hi, uint32_t& lo) {
    __nv_bfloat16 xa = __float2bfloat16(a), xb = __float2bfloat16(b);
    hi = pack2(__bfloat162float(xa), __bfloat162float(xb));
    lo = pack2(a - __bfloat162float(xa), b - __bfloat162float(xb));
}

// ---------------------------------------------------------------------------
// cvt_split / cvt_transpose_split (unchanged)
// ---------------------------------------------------------------------------
__global__ __launch_bounds__(256) void cvt_split(
    const float* __restrict__ in, __nv_bfloat16* __restrict__ hi,
    __nv_bfloat16* __restrict__ lo, int n4)
{
    int i = blockIdx.x * blockDim.x + threadIdx.x;
    if (i >= n4) return;
    float4 v = ((const float4*)in)[i];
    uint32_t h0, l0, h1, l1;
    split2(v.x, v.y, h0, l0);
    split2(v.z, v.w, h1, l1);
    ((uint32_t*)hi)[2 * i] = h0; ((uint32_t*)hi)[2 * i + 1] = h1;
    ((uint32_t*)lo)[2 * i] = l0; ((uint32_t*)lo)[2 * i + 1] = l1;
}

__global__ __launch_bounds__(256) void cvt_transpose_split(
    const float* __restrict__ W, __nv_bfloat16* __restrict__ oh,
    __nv_bfloat16* __restrict__ ol, int Kw, int Nw)
{
    __shared__ float t[32][33];
    int tx = threadIdx.x, ty = threadIdx.y;
    int n0 = blockIdx.x * 32, k0 = blockIdx.y * 32;
#pragma unroll
    for (int j = 0; j < 4; j++)
        t[ty + 8 * j][tx] = W[(size_t)(k0 + ty + 8 * j) * Nw + n0 + tx];
    __syncthreads();
#pragma unroll
    for (int j = 0; j < 4; j++) {
        float v = t[tx][ty + 8 * j];
        __nv_bfloat16 h = __float2bfloat16(v);
        __nv_bfloat16 l = __float2bfloat16(v - __bfloat162float(h));
        size_t idx = (size_t)(n0 + ty + 8 * j) * Kw + k0 + tx;
        oh[idx] = h; ol[idx] = l;
    }
}

// ---------------------------------------------------------------------------
// HMMA split-bf16 GEMM v2: CTA 128x128, 4 warps, warp tile 64x64, BK=32.
// 3-stage cp.async pipeline (32KB/stage = 96KB), single sync per iter.
// ---------------------------------------------------------------------------
#define HG_STAGE 32768

template <bool HAS_BIAS>
__global__ __launch_bounds__(128) void hgemm(
    const __nv_bfloat16* __restrict__ Ah, const __nv_bfloat16* __restrict__ Al,
    const __nv_bfloat16* __restrict__ Bh, const __nv_bfloat16* __restrict__ Bl,
    const float* __restrict__ bias, float* __restrict__ Cm, int N, int K)
{
    extern __shared__ __align__(1024) char smem[];
    const uint32_t sbase = smem_u32(smem);
    const int tid = threadIdx.x;
    const int lane = tid & 31;
    const int wid = tid >> 5;
    const int wm = (wid >> 1) * 64;
    const int wn = (wid & 1) * 64;
    const int brow = blockIdx.y * 128;
    const int bcol = blockIdx.x * 128;

    // loader: thread tid owns row tid of A and of B (8 chunks each: 4 hi + 4 lo)
    const __nv_bfloat16* Asrc_h = Ah + (size_t)(brow + tid) * K;
    const __nv_bfloat16* Asrc_l = Al + (size_t)(brow + tid) * K;
    const __nv_bfloat16* Bsrc_h = Bh + (size_t)(bcol + tid) * K;
    const __nv_bfloat16* Bsrc_l = Bl + (size_t)(bcol + tid) * K;
    uint32_t sd_h[4], sd_l[4];
#pragma unroll
    for (int j = 0; j < 4; j++) {
        sd_h[j] = swz(tid * 128 + j * 16);
        sd_l[j] = swz(tid * 128 + 64 + j * 16);
    }

    float acc[4][8][4];
#pragma unroll
    for (int mt = 0; mt < 4; mt++)
#pragma unroll
        for (int j = 0; j < 8; j++)
#pragma unroll
            for (int i = 0; i < 4; i++) acc[mt][j][i] = 0.f;

    const int T = K >> 5;

    // prologue: stages 0,1
#pragma unroll
    for (int s = 0; s < 2; s++) {
        uint32_t sA = sbase + s * HG_STAGE;
        uint32_t sB = sA + 16384;
#pragma unroll
        for (int j = 0; j < 4; j++) {
            cp16(sA + sd_h[j], Asrc_h + s * 32 + j * 8);
            cp16(sA + sd_l[j], Asrc_l + s * 32 + j * 8);
            cp16(sB + sd_h[j], Bsrc_h + s * 32 + j * 8);
            cp16(sB + sd_l[j], Bsrc_l + s * 32 + j * 8);
        }
        CP_COMMIT();
    }

    for (int t = 0; t < T; t++) {
        if (t + 1 < T) { CP_WAIT(1); } else { CP_WAIT(0); }
        __syncthreads();   // stage t visible; all warps past compute t-1

        // issue stage t+2 into buffer (t+2)%3 (freed by compute t-1)
        if (t + 2 < T) {
            uint32_t sA = sbase + ((t + 2) % 3) * HG_STAGE;
            uint32_t sB = sA + 16384;
#pragma unroll
            for (int j = 0; j < 4; j++) {
                cp16(sA + sd_h[j], Asrc_h + (t + 2) * 32 + j * 8);
                cp16(sA + sd_l[j], Asrc_l + (t + 2) * 32 + j * 8);
                cp16(sB + sd_h[j], Bsrc_h + (t + 2) * 32 + j * 8);
                cp16(sB + sd_l[j], Bsrc_l + (t + 2) * 32 + j * 8);
            }
            CP_COMMIT();
        }

        const uint32_t sA = sbase + (t % 3) * HG_STAGE;
        const uint32_t sB = sA + 16384;

#pragma unroll
        for (int ks = 0; ks < 2; ks++) {
            // B fragments: 8 n8-groups via 4 x4-ldmatrix per plane
            uint32_t bfh[8][2], bfl[8][2];
#pragma unroll
            for (int jp = 0; jp < 4; jp++) {
                uint32_t r4[4];
                uint32_t rowb = wn + jp * 16 + (lane & 7) + ((lane >> 4) << 3);
                uint32_t off = swz(rowb * 128 + ks * 32 + (((lane >> 3) & 1) << 4));
                ldsm4(r4, sB + off);
                bfh[2 * jp][0] = r4[0]; bfh[2 * jp][1] = r4[1];
                bfh[2 * jp + 1][0] = r4[2]; bfh[2 * jp + 1][1] = r4[3];
                uint32_t offl = swz(rowb * 128 + 64 + ks * 32 + (((lane >> 3) & 1) << 4));
                ldsm4(r4, sB + offl);
                bfl[2 * jp][0] = r4[0]; bfl[2 * jp][1] = r4[1];
                bfl[2 * jp + 1][0] = r4[2]; bfl[2 * jp + 1][1] = r4[3];
            }
#pragma unroll
            for (int mt = 0; mt < 4; mt++) {
                uint32_t ah[4], al[4];
                uint32_t rowa = wm + mt * 16 + (lane & 15);
                ldsm4(ah, sA + swz(rowa * 128 + ks * 32 + (lane >> 4) * 16));
                ldsm4(al, sA + swz(rowa * 128 + 64 + ks * 32 + (lane >> 4) * 16));
#pragma unroll
                for (int j = 0; j < 8; j++) {
                    mma16816(acc[mt][j], ah, bfh[j]);
                    mma16816(acc[mt][j], ah, bfl[j]);
                    mma16816(acc[mt][j], al, bfh[j]);
                }
            }
        }
    }

    // epilogue
#pragma unroll
    for (int mt = 0; mt < 4; mt++) {
        int r0 = brow + wm + mt * 16 + (lane >> 2);
#pragma unroll
        for (int j = 0; j < 8; j++) {
            int col = bcol + wn + j * 8 + (lane & 3) * 2;
            float bx = 0.f, by = 0.f;
            if (HAS_BIAS) { bx = bias[col]; by = bias[col + 1]; }
            *(float2*)(Cm + (size_t)r0 * N + col) =
                make_float2(acc[mt][j][0] + bx, acc[mt][j][1] + by);
            *(float2*)(Cm + (size_t)(r0 + 8) * N + col) =
                make_float2(acc[mt][j][2] + bx, acc[mt][j][3] + by);
        }
    }
}

// ---------------------------------------------------------------------------
// ln_split (unchanged)
// ---------------------------------------------------------------------------
__global__ __launch_bounds__(256) void ln_split(
    const float* __restrict__ qkv,
    const float* __restrict__ qw, const float* __restrict__ qb,
    const float* __restrict__ kw, const float* __restrict__ kb,
    __nv_bfloat16* __restrict__ qh, __nv_bfloat16* __restrict__ ql,
    __nv_bfloat16* __restrict__ kh, __nv_bfloat16* __restrict__ kl,
    __nv_bfloat16* __restrict__ vh, __nv_bfloat16* __restrict__ vl)
{
    int gwarp = (blockIdx.x * blockDim.x + threadIdx.x) >> 5;
    int lane = threadIdx.x & 31;
    const int ROWS = M_ * H_;
    int mtx = (gwarp >= 2 * ROWS) ? 2 : (gwarp >= ROWS ? 1 : 0);
    int r = gwarp - mtx * ROWS;
    int bn = r >> 4;
    int h = r & 15;
    const float* src = qkv + (size_t)bn * QKVN + mtx * C_ + h * HD_;

    float x0 = src[lane];
    float x1 = src[lane + 32];

    if (mtx < 2) {
        float s = x0 + x1;
#pragma unroll
        for (int o = 16; o > 0; o >>= 1) s += __shfl_xor_sync(0xffffffffu, s, o);
        float mu = s * (1.0f / 64.0f);
        float d0 = x0 - mu, d1 = x1 - mu;
        float v = d0 * d0 + d1 * d1;
#pragma unroll
        for (int o = 16; o > 0; o >>= 1) v += __shfl_xor_sync(0xffffffffu, v, o);
        float rinv = rsqrtf(v * (1.0f / 64.0f) + 1e-5f);
        const float* w = mtx == 0 ? qw : kw;
        const float* bb = mtx == 0 ? qb : kb;
        float sc = mtx == 0 ? (0.125f * LOG2E) : 1.0f;
        x0 = (d0 * rinv * w[lane] + bb[lane]) * sc;
        x1 = (d1 * rinv * w[lane + 32] + bb[lane + 32]) * sc;
    }

    int b = bn >> 11;
    int n = bn & (N_ - 1);
    size_t dst = ((size_t)(b * H_ + h) * N_ + n) * HD_;
    __nv_bfloat16* ph = mtx == 0 ? qh : (mtx == 1 ? kh : vh);
    __nv_bfloat16* pl = mtx == 0 ? ql : (mtx == 1 ? kl : vl);
    __nv_bfloat16 h0 = __float2bfloat16(x0);
    __nv_bfloat16 h1 = __float2bfloat16(x1);
    ph[dst + lane] = h0;
    ph[dst + lane + 32] = h1;
    pl[dst + lane] = __float2bfloat16(x0 - __bfloat162float(h0));
    pl[dst + lane + 32] = __float2bfloat16(x1 - __bfloat162float(h1));
}

// ---------------------------------------------------------------------------
// HMMA flash attention v2: 4 warps, 128 q rows/CTA (warp tile 32x64 over kv).
// smem: Q 32KB (hi 16 | lo 16) + 2 KV stages x 32KB = 96KB.
// K/V fragments shared across 2 m-tiles; x4 ldmatrix everywhere.
// ---------------------------------------------------------------------------
#define AT_Q_SZ 32768
#define AT_KV_STAGE 32768
#define AT_SMEM (AT_Q_SZ + 2 * AT_KV_STAGE)

__global__ __launch_bounds__(128) void attn_hmma(
    const __nv_bfloat16* __restrict__ qh, const __nv_bfloat16* __restrict__ ql,
    const __nv_bfloat16* __restrict__ kh, const __nv_bfloat16* __restrict__ kl,
    const __nv_bfloat16* __restrict__ vh, const __nv_bfloat16* __restrict__ vl,
    __nv_bfloat16* __restrict__ OH, __nv_bfloat16* __restrict__ OL)
{
    extern __shared__ __align__(1024) char smem[];
    const uint32_t sbase = smem_u32(smem);
    const int tid = threadIdx.x;
    const int lane = tid & 31;
    const int w = tid >> 5;
    const int bh = blockIdx.y;
    const int q0 = blockIdx.x * 128;
    const size_t base = (size_t)bh * N_ * HD_;

    // ---- prologue: Q (2048 chunks) + KV stage 0 (2048), then stage 1 ----
#pragma unroll
    for (int j = 0; j < 16; j++) {
        int id = tid * 16 + j;               // 2048 = Q chunks
        int pl = id >> 10, rem = id & 1023, row = rem >> 3, ch = rem & 7;
        cp16(sbase + pl * 16384 + swz(row * 128 + ch * 16),
             (pl ? ql : qh) + base + (size_t)(q0 + row) * HD_ + ch * 8);
    }
#pragma unroll
    for (int j = 0; j < 16; j++) {
        int id = tid * 16 + j;               // 2048 = KV chunks
        int buf = id >> 10, rem = id & 1023;
        int pl = rem >> 9, row = (rem >> 3) & 63, ch = rem & 7;
        const __nv_bfloat16* src = buf ? (pl ? vl : vh) : (pl ? kl : kh);
        cp16(sbase + AT_Q_SZ + buf * 16384 + pl * 8192 + swz(row * 128 + ch * 16),
             src + base + (size_t)row * HD_ + ch * 8);
    }
    CP_COMMIT();
#pragma unroll
    for (int j = 0; j < 16; j++) {
        int id = tid * 16 + j;
        int buf = id >> 10, rem = id & 1023;
        int pl = rem >> 9, row = (rem >> 3) & 63, ch = rem & 7;
        const __nv_bfloat16* src = buf ? (pl ? vl : vh) : (pl ? kl : kh);
        cp16(sbase + AT_Q_SZ + AT_KV_STAGE + buf * 16384 + pl * 8192 + swz(row * 128 + ch * 16),
             src + base + (size_t)(64 + row) * HD_ + ch * 8);
    }
    CP_COMMIT();

    float oac[2][8][4];
#pragma unroll
    for (int mt = 0; mt < 2; mt++)
#pragma unroll
        for (int j = 0; j < 8; j++)
#pragma unroll
            for (int i = 0; i < 4; i++) oac[mt][j][i] = 0.f;
    float mm[2][2], ll[2][2];
#pragma unroll
    for (int mt = 0; mt < 2; mt++) {
        mm[mt][0] = -INFINITY; mm[mt][1] = -INFINITY;
        ll[mt][0] = 0.f; ll[mt][1] = 0.f;
    }

    const int T = N_ / 64;
    for (int t = 0; t < T; t++) {
        if (t == T - 1) { CP_WAIT(0); } else { CP_WAIT(1); }
        __syncthreads();

        const uint32_t sK = sbase + AT_Q_SZ + (t & 1) * AT_KV_STAGE;
        const uint32_t sV = sK + 16384;

        // ---- S = Q @ K^T ----
        float s[2][8][4];
#pragma unroll
        for (int mt = 0; mt < 2; mt++)
#pragma unroll
            for (int j = 0; j < 8; j++)
#pragma unroll
                for (int i = 0; i < 4; i++) s[mt][j][i] = 0.f;

#pragma unroll
        for (int kt = 0; kt < 4; kt++) {
            uint32_t kfh[8][2], kfl[8][2];
#pragma unroll
            for (int jp = 0; jp < 4; jp++) {
                uint32_t r4[4];
                uint32_t rowb = jp * 16 + (lane & 7) + ((lane >> 4) << 3);
                uint32_t off = swz(rowb * 128 + kt * 32 + (((lane >> 3) & 1) << 4));
                ldsm4(r4, sK + off);
                kfh[2 * jp][0] = r4[0]; kfh[2 * jp][1] = r4[1];
                kfh[2 * jp + 1][0] = r4[2]; kfh[2 * jp + 1][1] = r4[3];
                ldsm4(r4, sK + 8192 + off);
                kfl[2 * jp][0] = r4[0]; kfl[2 * jp][1] = r4[1];
                kfl[2 * jp + 1][0] = r4[2]; kfl[2 * jp + 1][1] = r4[3];
            }
#pragma unroll
            for (int mt = 0; mt < 2; mt++) {
                uint32_t qf[4], qg[4];
                uint32_t rowa = w * 32 + mt * 16 + (lane & 15);
                uint32_t off = swz(rowa * 128 + kt * 32 + (lane >> 4) * 16);
                ldsm4(qf, sbase + off);
                ldsm4(qg, sbase + 16384 + off);
#pragma unroll
                for (int j = 0; j < 8; j++) {
                    mma16816(s[mt][j], qf, kfh[j]);
                    mma16816(s[mt][j], qf, kfl[j]);
                    mma16816(s[mt][j], qg, kfh[j]);
                }
            }
        }

        // ---- online softmax per m-tile ----
#pragma unroll
        for (int mt = 0; mt < 2; mt++) {
            float mx0 = -INFINITY, mx1 = -INFINITY;
#pragma unroll
            for (int j = 0; j < 8; j++) {
                mx0 = fmaxf(mx0, fmaxf(s[mt][j][0], s[mt][j][1]));
                mx1 = fmaxf(mx1, fmaxf(s[mt][j][2], s[mt][j][3]));
            }
            mx0 = fmaxf(mx0, __shfl_xor_sync(0xffffffffu, mx0, 1));
            mx0 = fmaxf(mx0, __shfl_xor_sync(0xffffffffu, mx0, 2));
            mx1 = fmaxf(mx1, __shfl_xor_sync(0xffffffffu, mx1, 1));
            mx1 = fmaxf(mx1, __shfl_xor_sync(0xffffffffu, mx1, 2));
            float mn0 = fmaxf(mm[mt][0], mx0), mn1 = fmaxf(mm[mt][1], mx1);
            float c0 = exp2f(mm[mt][0] - mn0), c1 = exp2f(mm[mt][1] - mn1);
            mm[mt][0] = mn0; mm[mt][1] = mn1;
            float rs0 = 0.f, rs1 = 0.f;
#pragma unroll
            for (int j = 0; j < 8; j++) {
                s[mt][j][0] = exp2f(s[mt][j][0] - mn0);
                s[mt][j][1] = exp2f(s[mt][j][1] - mn0);
                s[mt][j][2] = exp2f(s[mt][j][2] - mn1);
                s[mt][j][3] = exp2f(s[mt][j][3] - mn1);
                rs0 += s[mt][j][0] + s[mt][j][1];
                rs1 += s[mt][j][2] + s[mt][j][3];
            }
            rs0 += __shfl_xor_sync(0xffffffffu, rs0, 1);
            rs0 += __shfl_xor_sync(0xffffffffu, rs0, 2);
            rs1 += __shfl_xor_sync(0xffffffffu, rs1, 1);
            rs1 += __shfl_xor_sync(0xffffffffu, rs1, 2);
            ll[mt][0] = ll[mt][0] * c0 + rs0;
            ll[mt][1] = ll[mt][1] * c1 + rs1;
#pragma unroll
            for (int j = 0; j < 8; j++) {
                oac[mt][j][0] *= c0; oac[mt][j][1] *= c0;
                oac[mt][j][2] *= c1; oac[mt][j][3] *= c1;
            }
        }

        // ---- O += P @ V ----
#pragma unroll
        for (int kt2 = 0; kt2 < 4; kt2++) {
            uint32_t vfh[8][2], vfl[8][2];
#pragma unroll
            for (int hjp = 0; hjp < 4; hjp++) {
                uint32_t r4[4];
                uint32_t off = swz((kt2 * 16 + (lane & 15)) * 128 +
                                   hjp * 32 + (lane >> 4) * 16);
                ldsm4t(r4, sV + off);
                vfh[2 * hjp][0] = r4[0]; vfh[2 * hjp][1] = r4[1];
                vfh[2 * hjp + 1][0] = r4[2]; vfh[2 * hjp + 1][1] = r4[3];
                ldsm4t(r4, sV + 8192 + off);
                vfl[2 * hjp][0] = r4[0]; vfl[2 * hjp][1] = r4[1];
                vfl[2 * hjp + 1][0] = r4[2]; vfl[2 * hjp + 1][1] = r4[3];
            }
#pragma unroll
            for (int mt = 0; mt < 2; mt++) {
                uint32_t pfh[4], pfl[4];
                split2(s[mt][2 * kt2][0],     s[mt][2 * kt2][1],     pfh[0], pfl[0]);
                split2(s[mt][2 * kt2][2],     s[mt][2 * kt2][3],     pfh[1], pfl[1]);
                split2(s[mt][2 * kt2 + 1][0], s[mt][2 * kt2 + 1][1], pfh[2], pfl[2]);
                split2(s[mt][2 * kt2 + 1][2], s[mt][2 * kt2 + 1][3], pfh[3], pfl[3]);
#pragma unroll
                for (int hj = 0; hj < 8; hj++) {
                    mma16816(oac[mt][hj], pfh, vfh[hj]);
                    mma16816(oac[mt][hj], pfh, vfl[hj]);
                    mma16816(oac[mt][hj], pfl, vfh[hj]);
                }
            }
        }

        __syncthreads();
        if (t + 2 < T) {
            const uint32_t sKn = sbase + AT_Q_SZ + (t & 1) * AT_KV_STAGE;
#pragma unroll
            for (int j = 0; j < 16; j++) {
                int id = tid * 16 + j;
                int buf = id >> 10, rem = id & 1023;
                int pl = rem >> 9, row = (rem >> 3) & 63, ch = rem & 7;
                const __nv_bfloat16* src = buf ? (pl ? vl : vh) : (pl ? kl : kh);
                cp16(sKn + buf * 16384 + pl * 8192 + swz(row * 128 + ch * 16),
                     src + base + (size_t)((t + 2) * 64 + row) * HD_ + ch * 8);
            }
            CP_COMMIT();
        }
    }

    // ---- epilogue ----
    int b = bh >> 4, h = bh & 15;
#pragma unroll
    for (int mt = 0; mt < 2; mt++) {
        float il0 = 1.0f / ll[mt][0], il1 = 1.0f / ll[mt][1];
        int r0 = q0 + w * 32 + mt * 16 + (lane >> 2);
        size_t base0 = ((size_t)(b * N_) + r0) * C_ + h * HD_;
        size_t base1 = base0 + 8 * C_;
#pragma unroll
        for (int hj = 0; hj < 8; hj++) {
            int col = hj * 8 + (lane & 3) * 2;
            uint32_t hi, lo;
            split2(oac[mt][hj][0] * il0, oac[mt][hj][1] * il0, hi, lo);
            *(uint32_t*)(OH + base0 + col) = hi;
            *(uint32_t*)(OL + base0 + col) = lo;
            split2(oac[mt][hj][2] * il1, oac[mt][hj][3] * il1, hi, lo);
            *(uint32_t*)(OH + base1 + col) = hi;
            *(uint32_t*)(OL + base1 + col) = lo;
        }
    }
}

// ---------------------------------------------------------------------------
// Launch
// ---------------------------------------------------------------------------
extern "C" void kernel_launch(void* const* d_in, const int* in_sizes, int n_in,
                              void* d_out, int out_size)
{
    const float* x     = (const float*)d_in[0];
    const float* Wqkv  = (const float*)d_in[1];
    const float* qnw   = (const float*)d_in[2];
    const float* qnb   = (const float*)d_in[3];
    const float* knw   = (const float*)d_in[4];
    const float* knb   = (const float*)d_in[5];
    const float* Wproj = (const float*)d_in[6];
    const float* bproj = (const float*)d_in[7];
    float* out = (float*)d_out;

    float* qkv;
    __nv_bfloat16 *xh, *xl, *oh, *ol, *wqh, *wql, *wph, *wpl;
    __nv_bfloat16 *qh, *ql, *kh, *kl, *vh, *vl;
    cudaGetSymbolAddress((void**)&qkv, g_qkv);
    cudaGetSymbolAddress((void**)&xh, g_xh);
    cudaGetSymbolAddress((void**)&xl, g_xl);
    cudaGetSymbolAddress((void**)&oh, g_oh);
    cudaGetSymbolAddress((void**)&ol, g_ol);
    cudaGetSymbolAddress((void**)&wqh, g_wqkvT_h);
    cudaGetSymbolAddress((void**)&wql, g_wqkvT_l);
    cudaGetSymbolAddress((void**)&wph, g_wprojT_h);
    cudaGetSymbolAddress((void**)&wpl, g_wprojT_l);
    cudaGetSymbolAddress((void**)&qh, g_qh);
    cudaGetSymbolAddress((void**)&ql, g_ql);
    cudaGetSymbolAddress((void**)&kh, g_kh);
    cudaGetSymbolAddress((void**)&kl, g_kl);
    cudaGetSymbolAddress((void**)&vh, g_vh);
    cudaGetSymbolAddress((void**)&vl, g_vl);

    cudaFuncSetAttribute(hgemm<false>, cudaFuncAttributeMaxDynamicSharedMemorySize, 3 * HG_STAGE);
    cudaFuncSetAttribute(hgemm<true>, cudaFuncAttributeMaxDynamicSharedMemorySize, 3 * HG_STAGE);
    cudaFuncSetAttribute(attn_hmma, cudaFuncAttributeMaxDynamicSharedMemorySize, AT_SMEM);

    cvt_split<<<(M_ * C_ / 4 + 255) / 256, 256>>>(x, xh, xl, M_ * C_ / 4);
    cvt_transpose_split<<<dim3(QKVN / 32, C_ / 32), dim3(32, 8)>>>(Wqkv, wqh, wql, C_, QKVN);
    cvt_transpose_split<<<dim3(C_ / 32, C_ / 32), dim3(32, 8)>>>(Wproj, wph, wpl, C_, C_);

    hgemm<false><<<dim3(QKVN / 128, M_ / 128), 128, 3 * HG_STAGE>>>(
        xh, xl, wqh, wql, nullptr, qkv, QKVN, C_);

    ln_split<<<3 * M_ * H_ / 8, 256>>>(qkv, qnw, qnb, knw, knb,
                                       qh, ql, kh, kl, vh, vl);

    attn_hmma<<<dim3(N_ / 128, B_ * H_), 128, AT_SMEM>>>(qh, ql, kh, kl, vh, vl, oh, ol);

    hgemm<true><<<dim3(C_ / 128, M_ / 128), 128, 3 * HG_STAGE>>>(
        oh, ol, wph, wpl, bproj, out, C_, C_);
}

// round 5
// speedup vs baseline: 2.1687x; 1.0119x over previous
#include <cuda_runtime.h>
#include <cuda_bf16.h>
#include <math.h>
#include <stdint.h>

#define B_  2
#define N_  2048
#define C_  1024
#define H_  16
#define HD_ 64
#define M_  (B_ * N_)      // 4096
#define QKVN (3 * C_)      // 3072
#define LOG2E 1.4426950408889634f

// ---------------- scratch (static device globals) ----------------
static __device__ __align__(256) float g_qkv[M_ * QKVN];
static __device__ __align__(256) __nv_bfloat16 g_xh[M_ * C_];
static __device__ __align__(256) __nv_bfloat16 g_xl[M_ * C_];
static __device__ __align__(256) __nv_bfloat16 g_oh[M_ * C_];
static __device__ __align__(256) __nv_bfloat16 g_ol[M_ * C_];
static __device__ __align__(256) __nv_bfloat16 g_wqkvT_h[QKVN * C_];
static __device__ __align__(256) __nv_bfloat16 g_wqkvT_l[QKVN * C_];
static __device__ __align__(256) __nv_bfloat16 g_wprojT_h[C_ * C_];
static __device__ __align__(256) __nv_bfloat16 g_wprojT_l[C_ * C_];
static __device__ __align__(256) __nv_bfloat16 g_qh[M_ * C_];
static __device__ __align__(256) __nv_bfloat16 g_ql[M_ * C_];
static __device__ __align__(256) __nv_bfloat16 g_kh[M_ * C_];
static __device__ __align__(256) __nv_bfloat16 g_kl[M_ * C_];
static __device__ __align__(256) __nv_bfloat16 g_vh[M_ * C_];
static __device__ __align__(256) __nv_bfloat16 g_vl[M_ * C_];

// ---------------- helpers ----------------
__device__ __forceinline__ uint32_t smem_u32(const void* p) {
    uint32_t a;
    asm("{ .reg .u64 t; cvta.to.shared.u64 t, %1; cvt.u32.u64 %0, t; }" : "=r"(a) : "l"(p));
    return a;
}
__device__ __forceinline__ uint32_t swz(uint32_t o) { return o ^ ((o >> 3) & 0x70); }

__device__ __forceinline__ void cp16(uint32_t dst, const void* src) {
    asm volatile("cp.async.cg.shared.global [%0], [%1], 16;" :: "r"(dst), "l"(src) : "memory");
}
#define CP_COMMIT() asm volatile("cp.async.commit_group;" ::: "memory")
#define CP_WAIT(N)  asm volatile("cp.async.wait_group %0;" :: "n"(N) : "memory")

__device__ __forceinline__ void ldsm4(uint32_t* r, uint32_t a) {
    asm volatile("ldmatrix.sync.aligned.m8n8.x4.shared.b16 {%0,%1,%2,%3}, [%4];"
                 : "=r"(r[0]), "=r"(r[1]), "=r"(r[2]), "=r"(r[3]) : "r"(a));
}
__device__ __forceinline__ void ldsm4t(uint32_t* r, uint32_t a) {
    asm volatile("ldmatrix.sync.aligned.m8n8.x4.trans.shared.b16 {%0,%1,%2,%3}, [%4];"
                 : "=r"(r[0]), "=r"(r[1]), "=r"(r[2]), "=r"(r[3]) : "r"(a));
}
__device__ __forceinline__ void mma16816(float* c, const uint32_t* a, const uint32_t* b) {
    asm volatile(
        "mma.sync.aligned.m16n8k16.row.col.f32.bf16.bf16.f32 "
        "{%0,%1,%2,%3}, {%4,%5,%6,%7}, {%8,%9}, {%0,%1,%2,%3};"
        : "+f"(c[0]), "+f"(c[1]), "+f"(c[2]), "+f"(c[3])
        : "r"(a[0]), "r"(a[1]), "r"(a[2]), "r"(a[3]), "r"(b[0]), "r"(b[1]));
}
__device__ __forceinline__ uint32_t pack2(float lo, float hi) {
    uint32_t r;
    asm("cvt.rn.bf16x2.f32 %0, %1, %2;" : "=r"(r) : "f"(hi), "f"(lo));
    return r;
}
__device__ __forceinline__ void split2(float a, float b, uint32_t& hi, uint32_t& lo) {
    __nv_bfloat16 xa = __float2bfloat16(a), xb = __float2bfloat16(b);
    hi = pack2(__bfloat162float(xa), __bfloat162float(xb));
    lo = pack2(a - __bfloat162float(xa), b - __bfloat162float(xb));
}

// ---------------------------------------------------------------------------
// cvt_split / cvt_transpose_split
// ---------------------------------------------------------------------------
__global__ __launch_bounds__(256) void cvt_split(
    const float* __restrict__ in, __nv_bfloat16* __restrict__ hi,
    __nv_bfloat16* __restrict__ lo, int n4)
{
    int i = blockIdx.x * blockDim.x + threadIdx.x;
    if (i >= n4) return;
    float4 v = ((const float4*)in)[i];
    uint32_t h0, l0, h1, l1;
    split2(v.x, v.y, h0, l0);
    split2(v.z, v.w, h1, l1);
    ((uint32_t*)hi)[2 * i] = h0; ((uint32_t*)hi)[2 * i + 1] = h1;
    ((uint32_t*)lo)[2 * i] = l0; ((uint32_t*)lo)[2 * i + 1] = l1;
}

__global__ __launch_bounds__(256) void cvt_transpose_split(
    const float* __restrict__ W, __nv_bfloat16* __restrict__ oh,
    __nv_bfloat16* __restrict__ ol, int Kw, int Nw)
{
    __shared__ float t[32][33];
    int tx = threadIdx.x, ty = threadIdx.y;
    int n0 = blockIdx.x * 32, k0 = blockIdx.y * 32;
#pragma unroll
    for (int j = 0; j < 4; j++)
        t[ty + 8 * j][tx] = W[(size_t)(k0 + ty + 8 * j) * Nw + n0 + tx];
    __syncthreads();
#pragma unroll
    for (int j = 0; j < 4; j++) {
        float v = t[tx][ty + 8 * j];
        __nv_bfloat16 h = __float2bfloat16(v);
        __nv_bfloat16 l = __float2bfloat16(v - __bfloat162float(h));
        size_t idx = (size_t)(n0 + ty + 8 * j) * Kw + k0 + tx;
        oh[idx] = h; ol[idx] = l;
    }
}

// ---------------------------------------------------------------------------
// HMMA split-bf16 GEMM v3: CTA 128x128, 4 warps, warp tile 64x64, BK=32.
// 3-stage cp.async pipeline; MMA issue reordered by split-product so
// dependent writes to the same accumulator are >=16 MMAs apart.
// ---------------------------------------------------------------------------
#define HG_STAGE 32768

template <bool HAS_BIAS>
__global__ __launch_bounds__(128) void hgemm(
    const __nv_bfloat16* __restrict__ Ah, const __nv_bfloat16* __restrict__ Al,
    const __nv_bfloat16* __restrict__ Bh, const __nv_bfloat16* __restrict__ Bl,
    const float* __restrict__ bias, float* __restrict__ Cm, int N, int K)
{
    extern __shared__ __align__(1024) char smem[];
    const uint32_t sbase = smem_u32(smem);
    const int tid = threadIdx.x;
    const int lane = tid & 31;
    const int wid = tid >> 5;
    const int wm = (wid >> 1) * 64;
    const int wn = (wid & 1) * 64;
    const int brow = blockIdx.y * 128;
    const int bcol = blockIdx.x * 128;

    const __nv_bfloat16* Asrc_h = Ah + (size_t)(brow + tid) * K;
    const __nv_bfloat16* Asrc_l = Al + (size_t)(brow + tid) * K;
    const __nv_bfloat16* Bsrc_h = Bh + (size_t)(bcol + tid) * K;
    const __nv_bfloat16* Bsrc_l = Bl + (size_t)(bcol + tid) * K;
    uint32_t sd_h[4], sd_l[4];
#pragma unroll
    for (int j = 0; j < 4; j++) {
        sd_h[j] = swz(tid * 128 + j * 16);
        sd_l[j] = swz(tid * 128 + 64 + j * 16);
    }

    float acc[4][8][4];
#pragma unroll
    for (int mt = 0; mt < 4; mt++)
#pragma unroll
        for (int j = 0; j < 8; j++)
#pragma unroll
            for (int i = 0; i < 4; i++) acc[mt][j][i] = 0.f;

    const int T = K >> 5;

#pragma unroll
    for (int s = 0; s < 2; s++) {
        uint32_t sA = sbase + s * HG_STAGE;
        uint32_t sB = sA + 16384;
#pragma unroll
        for (int j = 0; j < 4; j++) {
            cp16(sA + sd_h[j], Asrc_h + s * 32 + j * 8);
            cp16(sA + sd_l[j], Asrc_l + s * 32 + j * 8);
            cp16(sB + sd_h[j], Bsrc_h + s * 32 + j * 8);
            cp16(sB + sd_l[j], Bsrc_l + s * 32 + j * 8);
        }
        CP_COMMIT();
    }

    for (int t = 0; t < T; t++) {
        if (t + 1 < T) { CP_WAIT(1); } else { CP_WAIT(0); }
        __syncthreads();

        if (t + 2 < T) {
            uint32_t sA = sbase + ((t + 2) % 3) * HG_STAGE;
            uint32_t sB = sA + 16384;
#pragma unroll
            for (int j = 0; j < 4; j++) {
                cp16(sA + sd_h[j], Asrc_h + (t + 2) * 32 + j * 8);
                cp16(sA + sd_l[j], Asrc_l + (t + 2) * 32 + j * 8);
                cp16(sB + sd_h[j], Bsrc_h + (t + 2) * 32 + j * 8);
                cp16(sB + sd_l[j], Bsrc_l + (t + 2) * 32 + j * 8);
            }
            CP_COMMIT();
        }

        const uint32_t sA = sbase + (t % 3) * HG_STAGE;
        const uint32_t sB = sA + 16384;

#pragma unroll
        for (int ks = 0; ks < 2; ks++) {
            uint32_t bfh[8][2], bfl[8][2];
#pragma unroll
            for (int jp = 0; jp < 4; jp++) {
                uint32_t r4[4];
                uint32_t rowb = wn + jp * 16 + (lane & 7) + ((lane >> 4) << 3);
                uint32_t off = swz(rowb * 128 + ks * 32 + (((lane >> 3) & 1) << 4));
                ldsm4(r4, sB + off);
                bfh[2 * jp][0] = r4[0]; bfh[2 * jp][1] = r4[1];
                bfh[2 * jp + 1][0] = r4[2]; bfh[2 * jp + 1][1] = r4[3];
                uint32_t offl = swz(rowb * 128 + 64 + ks * 32 + (((lane >> 3) & 1) << 4));
                ldsm4(r4, sB + offl);
                bfl[2 * jp][0] = r4[0]; bfl[2 * jp][1] = r4[1];
                bfl[2 * jp + 1][0] = r4[2]; bfl[2 * jp + 1][1] = r4[3];
            }
            // process m-tiles in pairs: 3 product sweeps of 16 independent MMAs
#pragma unroll
            for (int mp = 0; mp < 2; mp++) {
                uint32_t ah[2][4], al[2][4];
#pragma unroll
                for (int m2 = 0; m2 < 2; m2++) {
                    uint32_t rowa = wm + (mp * 2 + m2) * 16 + (lane & 15);
                    ldsm4(ah[m2], sA + swz(rowa * 128 + ks * 32 + (lane >> 4) * 16));
                    ldsm4(al[m2], sA + swz(rowa * 128 + 64 + ks * 32 + (lane >> 4) * 16));
                }
#pragma unroll
                for (int m2 = 0; m2 < 2; m2++)
#pragma unroll
                    for (int j = 0; j < 8; j++)
                        mma16816(acc[mp * 2 + m2][j], ah[m2], bfh[j]);
#pragma unroll
                for (int m2 = 0; m2 < 2; m2++)
#pragma unroll
                    for (int j = 0; j < 8; j++)
                        mma16816(acc[mp * 2 + m2][j], ah[m2], bfl[j]);
#pragma unroll
                for (int m2 = 0; m2 < 2; m2++)
#pragma unroll
                    for (int j = 0; j < 8; j++)
                        mma16816(acc[mp * 2 + m2][j], al[m2], bfh[j]);
            }
        }
    }

    // epilogue
#pragma unroll
    for (int mt = 0; mt < 4; mt++) {
        int r0 = brow + wm + mt * 16 + (lane >> 2);
#pragma unroll
        for (int j = 0; j < 8; j++) {
            int col = bcol + wn + j * 8 + (lane & 3) * 2;
            float bx = 0.f, by = 0.f;
            if (HAS_BIAS) { bx = bias[col]; by = bias[col + 1]; }
            *(float2*)(Cm + (size_t)r0 * N + col) =
                make_float2(acc[mt][j][0] + bx, acc[mt][j][1] + by);
            *(float2*)(Cm + (size_t)(r0 + 8) * N + col) =
                make_float2(acc[mt][j][2] + bx, acc[mt][j][3] + by);
        }
    }
}

// ---------------------------------------------------------------------------
// ln_split (unchanged)
// ---------------------------------------------------------------------------
__global__ __launch_bounds__(256) void ln_split(
    const float* __restrict__ qkv,
    const float* __restrict__ qw, const float* __restrict__ qb,
    const float* __restrict__ kw, const float* __restrict__ kb,
    __nv_bfloat16* __restrict__ qh, __nv_bfloat16* __restrict__ ql,
    __nv_bfloat16* __restrict__ kh, __nv_bfloat16* __restrict__ kl,
    __nv_bfloat16* __restrict__ vh, __nv_bfloat16* __restrict__ vl)
{
    int gwarp = (blockIdx.x * blockDim.x + threadIdx.x) >> 5;
    int lane = threadIdx.x & 31;
    const int ROWS = M_ * H_;
    int mtx = (gwarp >= 2 * ROWS) ? 2 : (gwarp >= ROWS ? 1 : 0);
    int r = gwarp - mtx * ROWS;
    int bn = r >> 4;
    int h = r & 15;
    const float* src = qkv + (size_t)bn * QKVN + mtx * C_ + h * HD_;

    float x0 = src[lane];
    float x1 = src[lane + 32];

    if (mtx < 2) {
        float s = x0 + x1;
#pragma unroll
        for (int o = 16; o > 0; o >>= 1) s += __shfl_xor_sync(0xffffffffu, s, o);
        float mu = s * (1.0f / 64.0f);
        float d0 = x0 - mu, d1 = x1 - mu;
        float v = d0 * d0 + d1 * d1;
#pragma unroll
        for (int o = 16; o > 0; o >>= 1) v += __shfl_xor_sync(0xffffffffu, v, o);
        float rinv = rsqrtf(v * (1.0f / 64.0f) + 1e-5f);
        const float* w = mtx == 0 ? qw : kw;
        const float* bb = mtx == 0 ? qb : kb;
        float sc = mtx == 0 ? (0.125f * LOG2E) : 1.0f;
        x0 = (d0 * rinv * w[lane] + bb[lane]) * sc;
        x1 = (d1 * rinv * w[lane + 32] + bb[lane + 32]) * sc;
    }

    int b = bn >> 11;
    int n = bn & (N_ - 1);
    size_t dst = ((size_t)(b * H_ + h) * N_ + n) * HD_;
    __nv_bfloat16* ph = mtx == 0 ? qh : (mtx == 1 ? kh : vh);
    __nv_bfloat16* pl = mtx == 0 ? ql : (mtx == 1 ? kl : vl);
    __nv_bfloat16 h0 = __float2bfloat16(x0);
    __nv_bfloat16 h1 = __float2bfloat16(x1);
    ph[dst + lane] = h0;
    ph[dst + lane + 32] = h1;
    pl[dst + lane] = __float2bfloat16(x0 - __bfloat162float(h0));
    pl[dst + lane + 32] = __float2bfloat16(x1 - __bfloat162float(h1));
}

// ---------------------------------------------------------------------------
// HMMA flash attention v3: same structure, MMA issue reordered by product.
// ---------------------------------------------------------------------------
#define AT_Q_SZ 32768
#define AT_KV_STAGE 32768
#define AT_SMEM (AT_Q_SZ + 2 * AT_KV_STAGE)

__global__ __launch_bounds__(128) void attn_hmma(
    const __nv_bfloat16* __restrict__ qh, const __nv_bfloat16* __restrict__ ql,
    const __nv_bfloat16* __restrict__ kh, const __nv_bfloat16* __restrict__ kl,
    const __nv_bfloat16* __restrict__ vh, const __nv_bfloat16* __restrict__ vl,
    __nv_bfloat16* __restrict__ OH, __nv_bfloat16* __restrict__ OL)
{
    extern __shared__ __align__(1024) char smem[];
    const uint32_t sbase = smem_u32(smem);
    const int tid = threadIdx.x;
    const int lane = tid & 31;
    const int w = tid >> 5;
    const int bh = blockIdx.y;
    const int q0 = blockIdx.x * 128;
    const size_t base = (size_t)bh * N_ * HD_;

#pragma unroll
    for (int j = 0; j < 16; j++) {
        int id = tid * 16 + j;
        int pl = id >> 10, rem = id & 1023, row = rem >> 3, ch = rem & 7;
        cp16(sbase + pl * 16384 + swz(row * 128 + ch * 16),
             (pl ? ql : qh) + base + (size_t)(q0 + row) * HD_ + ch * 8);
    }
#pragma unroll
    for (int j = 0; j < 16; j++) {
        int id = tid * 16 + j;
        int buf = id >> 10, rem = id & 1023;
        int pl = rem >> 9, row = (rem >> 3) & 63, ch = rem & 7;
        const __nv_bfloat16* src = buf ? (pl ? vl : vh) : (pl ? kl : kh);
        cp16(sbase + AT_Q_SZ + buf * 16384 + pl * 8192 + swz(row * 128 + ch * 16),
             src + base + (size_t)row * HD_ + ch * 8);
    }
    CP_COMMIT();
#pragma unroll
    for (int j = 0; j < 16; j++) {
        int id = tid * 16 + j;
        int buf = id >> 10, rem = id & 1023;
        int pl = rem >> 9, row = (rem >> 3) & 63, ch = rem & 7;
        const __nv_bfloat16* src = buf ? (pl ? vl : vh) : (pl ? kl : kh);
        cp16(sbase + AT_Q_SZ + AT_KV_STAGE + buf * 16384 + pl * 8192 + swz(row * 128 + ch * 16),
             src + base + (size_t)(64 + row) * HD_ + ch * 8);
    }
    CP_COMMIT();

    float oac[2][8][4];
#pragma unroll
    for (int mt = 0; mt < 2; mt++)
#pragma unroll
        for (int j = 0; j < 8; j++)
#pragma unroll
            for (int i = 0; i < 4; i++) oac[mt][j][i] = 0.f;
    float mm[2][2], ll[2][2];
#pragma unroll
    for (int mt = 0; mt < 2; mt++) {
        mm[mt][0] = -INFINITY; mm[mt][1] = -INFINITY;
        ll[mt][0] = 0.f; ll[mt][1] = 0.f;
    }

    const int T = N_ / 64;
    for (int t = 0; t < T; t++) {
        if (t == T - 1) { CP_WAIT(0); } else { CP_WAIT(1); }
        __syncthreads();

        const uint32_t sK = sbase + AT_Q_SZ + (t & 1) * AT_KV_STAGE;
        const uint32_t sV = sK + 16384;

        // ---- S = Q @ K^T ----
        float s[2][8][4];
#pragma unroll
        for (int mt = 0; mt < 2; mt++)
#pragma unroll
            for (int j = 0; j < 8; j++)
#pragma unroll
                for (int i = 0; i < 4; i++) s[mt][j][i] = 0.f;

#pragma unroll
        for (int kt = 0; kt < 4; kt++) {
            uint32_t kfh[8][2], kfl[8][2];
#pragma unroll
            for (int jp = 0; jp < 4; jp++) {
                uint32_t r4[4];
                uint32_t rowb = jp * 16 + (lane & 7) + ((lane >> 4) << 3);
                uint32_t off = swz(rowb * 128 + kt * 32 + (((lane >> 3) & 1) << 4));
                ldsm4(r4, sK + off);
                kfh[2 * jp][0] = r4[0]; kfh[2 * jp][1] = r4[1];
                kfh[2 * jp + 1][0] = r4[2]; kfh[2 * jp + 1][1] = r4[3];
                ldsm4(r4, sK + 8192 + off);
                kfl[2 * jp][0] = r4[0]; kfl[2 * jp][1] = r4[1];
                kfl[2 * jp + 1][0] = r4[2]; kfl[2 * jp + 1][1] = r4[3];
            }
            uint32_t qf[2][4], qg[2][4];
#pragma unroll
            for (int mt = 0; mt < 2; mt++) {
                uint32_t rowa = w * 32 + mt * 16 + (lane & 15);
                uint32_t off = swz(rowa * 128 + kt * 32 + (lane >> 4) * 16);
                ldsm4(qf[mt], sbase + off);
                ldsm4(qg[mt], sbase + 16384 + off);
            }
            // 3 product sweeps, 16 independent MMAs each
#pragma unroll
            for (int mt = 0; mt < 2; mt++)
#pragma unroll
                for (int j = 0; j < 8; j++)
                    mma16816(s[mt][j], qf[mt], kfh[j]);
#pragma unroll
            for (int mt = 0; mt < 2; mt++)
#pragma unroll
                for (int j = 0; j < 8; j++)
                    mma16816(s[mt][j], qf[mt], kfl[j]);
#pragma unroll
            for (int mt = 0; mt < 2; mt++)
#pragma unroll
                for (int j = 0; j < 8; j++)
                    mma16816(s[mt][j], qg[mt], kfh[j]);
        }

        // ---- online softmax per m-tile ----
#pragma unroll
        for (int mt = 0; mt < 2; mt++) {
            float mx0 = -INFINITY, mx1 = -INFINITY;
#pragma unroll
            for (int j = 0; j < 8; j++) {
                mx0 = fmaxf(mx0, fmaxf(s[mt][j][0], s[mt][j][1]));
                mx1 = fmaxf(mx1, fmaxf(s[mt][j][2], s[mt][j][3]));
            }
            mx0 = fmaxf(mx0, __shfl_xor_sync(0xffffffffu, mx0, 1));
            mx0 = fmaxf(mx0, __shfl_xor_sync(0xffffffffu, mx0, 2));
            mx1 = fmaxf(mx1, __shfl_xor_sync(0xffffffffu, mx1, 1));
            mx1 = fmaxf(mx1, __shfl_xor_sync(0xffffffffu, mx1, 2));
            float mn0 = fmaxf(mm[mt][0], mx0), mn1 = fmaxf(mm[mt][1], mx1);
            float c0 = exp2f(mm[mt][0] - mn0), c1 = exp2f(mm[mt][1] - mn1);
            mm[mt][0] = mn0; mm[mt][1] = mn1;
            float rs0 = 0.f, rs1 = 0.f;
#pragma unroll
            for (int j = 0; j < 8; j++) {
                s[mt][j][0] = exp2f(s[mt][j][0] - mn0);
                s[mt][j][1] = exp2f(s[mt][j][1] - mn0);
                s[mt][j][2] = exp2f(s[mt][j][2] - mn1);
                s[mt][j][3] = exp2f(s[mt][j][3] - mn1);
                rs0 += s[mt][j][0] + s[mt][j][1];
                rs1 += s[mt][j][2] + s[mt][j][3];
            }
            rs0 += __shfl_xor_sync(0xffffffffu, rs0, 1);
            rs0 += __shfl_xor_sync(0xffffffffu, rs0, 2);
            rs1 += __shfl_xor_sync(0xffffffffu, rs1, 1);
            rs1 += __shfl_xor_sync(0xffffffffu, rs1, 2);
            ll[mt][0] = ll[mt][0] * c0 + rs0;
            ll[mt][1] = ll[mt][1] * c1 + rs1;
#pragma unroll
            for (int j = 0; j < 8; j++) {
                oac[mt][j][0] *= c0; oac[mt][j][1] *= c0;
                oac[mt][j][2] *= c1; oac[mt][j][3] *= c1;
            }
        }

        // ---- O += P @ V ----
#pragma unroll
        for (int kt2 = 0; kt2 < 4; kt2++) {
            uint32_t vfh[8][2], vfl[8][2];
#pragma unroll
            for (int hjp = 0; hjp < 4; hjp++) {
                uint32_t r4[4];
                uint32_t off = swz((kt2 * 16 + (lane & 15)) * 128 +
                                   hjp * 32 + (lane >> 4) * 16);
                ldsm4t(r4, sV + off);
                vfh[2 * hjp][0] = r4[0]; vfh[2 * hjp][1] = r4[1];
                vfh[2 * hjp + 1][0] = r4[2]; vfh[2 * hjp + 1][1] = r4[3];
                ldsm4t(r4, sV + 8192 + off);
                vfl[2 * hjp][0] = r4[0]; vfl[2 * hjp][1] = r4[1];
                vfl[2 * hjp + 1][0] = r4[2]; vfl[2 * hjp + 1][1] = r4[3];
            }
            uint32_t pfh[2][4], pfl[2][4];
#pragma unroll
            for (int mt = 0; mt < 2; mt++) {
                split2(s[mt][2 * kt2][0],     s[mt][2 * kt2][1],     pfh[mt][0], pfl[mt][0]);
                split2(s[mt][2 * kt2][2],     s[mt][2 * kt2][3],     pfh[mt][1], pfl[mt][1]);
                split2(s[mt][2 * kt2 + 1][0], s[mt][2 * kt2 + 1][1], pfh[mt][2], pfl[mt][2]);
                split2(s[mt][2 * kt2 + 1][2], s[mt][2 * kt2 + 1][3], pfh[mt][3], pfl[mt][3]);
            }
#pragma unroll
            for (int mt = 0; mt < 2; mt++)
#pragma unroll
                for (int hj = 0; hj < 8; hj++)
                    mma16816(oac[mt][hj], pfh[mt], vfh[hj]);
#pragma unroll
            for (int mt = 0; mt < 2; mt++)
#pragma unroll
                for (int hj = 0; hj < 8; hj++)
                    mma16816(oac[mt][hj], pfh[mt], vfl[hj]);
#pragma unroll
            for (int mt = 0; mt < 2; mt++)
#pragma unroll
                for (int hj = 0; hj < 8; hj++)
                    mma16816(oac[mt][hj], pfl[mt], vfh[hj]);
        }

        __syncthreads();
        if (t + 2 < T) {
            const uint32_t sKn = sbase + AT_Q_SZ + (t & 1) * AT_KV_STAGE;
#pragma unroll
            for (int j = 0; j < 16; j++) {
                int id = tid * 16 + j;
                int buf = id >> 10, rem = id & 1023;
                int pl = rem >> 9, row = (rem >> 3) & 63, ch = rem & 7;
                const __nv_bfloat16* src = buf ? (pl ? vl : vh) : (pl ? kl : kh);
                cp16(sKn + buf * 16384 + pl * 8192 + swz(row * 128 + ch * 16),
                     src + base + (size_t)((t + 2) * 64 + row) * HD_ + ch * 8);
            }
            CP_COMMIT();
        }
    }

    // ---- epilogue ----
    int b = bh >> 4, h = bh & 15;
#pragma unroll
    for (int mt = 0; mt < 2; mt++) {
        float il0 = 1.0f / ll[mt][0], il1 = 1.0f / ll[mt][1];
        int r0 = q0 + w * 32 + mt * 16 + (lane >> 2);
        size_t base0 = ((size_t)(b * N_) + r0) * C_ + h * HD_;
        size_t base1 = base0 + 8 * C_;
#pragma unroll
        for (int hj = 0; hj < 8; hj++) {
            int col = hj * 8 + (lane & 3) * 2;
            uint32_t hi, lo;
            split2(oac[mt][hj][0] * il0, oac[mt][hj][1] * il0, hi, lo);
            *(uint32_t*)(OH + base0 + col) = hi;
            *(uint32_t*)(OL + base0 + col) = lo;
            split2(oac[mt][hj][2] * il1, oac[mt][hj][3] * il1, hi, lo);
            *(uint32_t*)(OH + base1 + col) = hi;
            *(uint32_t*)(OL + base1 + col) = lo;
        }
    }
}

// ---------------------------------------------------------------------------
// Launch
// ---------------------------------------------------------------------------
extern "C" void kernel_launch(void* const* d_in, const int* in_sizes, int n_in,
                              void* d_out, int out_size)
{
    const float* x     = (const float*)d_in[0];
    const float* Wqkv  = (const float*)d_in[1];
    const float* qnw   = (const float*)d_in[2];
    const float* qnb   = (const float*)d_in[3];
    const float* knw   = (const float*)d_in[4];
    const float* knb   = (const float*)d_in[5];
    const float* Wproj = (const float*)d_in[6];
    const float* bproj = (const float*)d_in[7];
    float* out = (float*)d_out;

    float* qkv;
    __nv_bfloat16 *xh, *xl, *oh, *ol, *wqh, *wql, *wph, *wpl;
    __nv_bfloat16 *qh, *ql, *kh, *kl, *vh, *vl;
    cudaGetSymbolAddress((void**)&qkv, g_qkv);
    cudaGetSymbolAddress((void**)&xh, g_xh);
    cudaGetSymbolAddress((void**)&xl, g_xl);
    cudaGetSymbolAddress((void**)&oh, g_oh);
    cudaGetSymbolAddress((void**)&ol, g_ol);
    cudaGetSymbolAddress((void**)&wqh, g_wqkvT_h);
    cudaGetSymbolAddress((void**)&wql, g_wqkvT_l);
    cudaGetSymbolAddress((void**)&wph, g_wprojT_h);
    cudaGetSymbolAddress((void**)&wpl, g_wprojT_l);
    cudaGetSymbolAddress((void**)&qh, g_qh);
    cudaGetSymbolAddress((void**)&ql, g_ql);
    cudaGetSymbolAddress((void**)&kh, g_kh);
    cudaGetSymbolAddress((void**)&kl, g_kl);
    cudaGetSymbolAddress((void**)&vh, g_vh);
    cudaGetSymbolAddress((void**)&vl, g_vl);

    cudaFuncSetAttribute(hgemm<false>, cudaFuncAttributeMaxDynamicSharedMemorySize, 3 * HG_STAGE);
    cudaFuncSetAttribute(hgemm<true>, cudaFuncAttributeMaxDynamicSharedMemorySize, 3 * HG_STAGE);
    cudaFuncSetAttribute(attn_hmma, cudaFuncAttributeMaxDynamicSharedMemorySize, AT_SMEM);

    cvt_split<<<(M_ * C_ / 4 + 255) / 256, 256>>>(x, xh, xl, M_ * C_ / 4);
    cvt_transpose_split<<<dim3(QKVN / 32, C_ / 32), dim3(32, 8)>>>(Wqkv, wqh, wql, C_, QKVN);
    cvt_transpose_split<<<dim3(C_ / 32, C_ / 32), dim3(32, 8)>>>(Wproj, wph, wpl, C_, C_);

    hgemm<false><<<dim3(QKVN / 128, M_ / 128), 128, 3 * HG_STAGE>>>(
        xh, xl, wqh, wql, nullptr, qkv, QKVN, C_);

    ln_split<<<3 * M_ * H_ / 8, 256>>>(qkv, qnw, qnb, knw, knb,
                                       qh, ql, kh, kl, vh, vl);

    attn_hmma<<<dim3(N_ / 128, B_ * H_), 128, AT_SMEM>>>(qh, ql, kh, kl, vh, vl, oh, ol);

    hgemm<true><<<dim3(C_ / 128, M_ / 128), 128, 3 * HG_STAGE>>>(
        oh, ol, wph, wpl, bproj, out, C_, C_);
}